// round 6
// baseline (speedup 1.0000x reference)
#include <cuda_runtime.h>
#include <cuda_bf16.h>
#include <cstdint>
#include <cstddef>

#define NN   50000
#define NE   800000
#define DIN  256
#define DHID 256
#define DOUT 128

#define SCAN_B 256
#define SCAN_GRID ((NN + SCAN_B - 1) / SCAN_B)   // 196

// ---------------- scratch (device globals; no allocation allowed) ----------------
__device__ float g_outnorm[NN];
__device__ float g_innorm[NN];
__device__ int   g_outc[NN];
__device__ int   g_inc[NN];
__device__ int   g_rowptr[NN + 1];
__device__ int   g_cursor[NN];
__device__ int   g_poff[SCAN_B];             // block partial sums -> exclusive offsets
__device__ int   g_csrc[NE];                 // src node per CSR slot (grouped by dst)
__device__ float g_t[(size_t)NN * DHID];     // pre-aggregation transformed features

// ---------------- degree / norm / CSR kernels ----------------
__global__ void k_zero_counts() {
    int i = blockIdx.x * blockDim.x + threadIdx.x;
    if (i < NN) { g_outc[i] = 0; g_inc[i] = 0; }
}

__global__ void k_degree(const int* __restrict__ src, const int* __restrict__ dst) {
    int e = blockIdx.x * blockDim.x + threadIdx.x;
    if (e < NE) {
        atomicAdd(&g_outc[src[e]], 1);
        atomicAdd(&g_inc[dst[e]], 1);
    }
}

__global__ void k_fin_norms() {
    int i = blockIdx.x * blockDim.x + threadIdx.x;
    if (i < NN) {
        g_outnorm[i] = rsqrtf(fmaxf((float)g_outc[i], 1.f));
        g_innorm[i]  = rsqrtf(fmaxf((float)g_inc[i], 1.f));
    }
}

// ---- 3-phase multi-block exclusive scan of g_inc -> g_rowptr / g_cursor ----
// phase 1: per-block sums
__global__ void k_scan_p1() {
    __shared__ int ws[8];
    int i = blockIdx.x * SCAN_B + threadIdx.x;
    int lane = threadIdx.x & 31, wid = threadIdx.x >> 5;
    int v = (i < NN) ? g_inc[i] : 0;
#pragma unroll
    for (int o = 16; o > 0; o >>= 1) v += __shfl_down_sync(0xffffffffu, v, o);
    if (lane == 0) ws[wid] = v;
    __syncthreads();
    if (wid == 0) {
        int s = (lane < 8) ? ws[lane] : 0;
#pragma unroll
        for (int o = 4; o > 0; o >>= 1) s += __shfl_down_sync(0xffffffffu, s, o);
        if (lane == 0) g_poff[blockIdx.x] = s;
    }
}

// phase 2: single-block exclusive scan of SCAN_GRID partials
__global__ void k_scan_p2() {
    __shared__ int ws[8];
    int tid = threadIdx.x, lane = tid & 31, wid = tid >> 5;
    int v = (tid < SCAN_GRID) ? g_poff[tid] : 0;
    int x = v;
#pragma unroll
    for (int o = 1; o < 32; o <<= 1) {
        int y = __shfl_up_sync(0xffffffffu, x, o);
        if (lane >= o) x += y;
    }
    if (lane == 31) ws[wid] = x;
    __syncthreads();
    if (wid == 0 && lane < 8) {
        int s = ws[lane];
        int xs = s;
#pragma unroll
        for (int o = 1; o < 8; o <<= 1) {
            int y = __shfl_up_sync(0xffu, xs, o);
            if (lane >= o) xs += y;
        }
        ws[lane] = xs - s;   // exclusive warp offsets
    }
    __syncthreads();
    g_poff[tid] = ws[wid] + x - v;   // exclusive offset for block tid
}

// phase 3: per-block exclusive scan + global offset
__global__ void k_scan_p3() {
    __shared__ int ws[8];
    int i = blockIdx.x * SCAN_B + threadIdx.x;
    int lane = threadIdx.x & 31, wid = threadIdx.x >> 5;
    int v = (i < NN) ? g_inc[i] : 0;
    int x = v;
#pragma unroll
    for (int o = 1; o < 32; o <<= 1) {
        int y = __shfl_up_sync(0xffffffffu, x, o);
        if (lane >= o) x += y;
    }
    if (lane == 31) ws[wid] = x;
    __syncthreads();
    if (wid == 0 && lane < 8) {
        int s = ws[lane];
        int xs = s;
#pragma unroll
        for (int o = 1; o < 8; o <<= 1) {
            int y = __shfl_up_sync(0xffu, xs, o);
            if (lane >= o) xs += y;
        }
        ws[lane] = xs - s;
    }
    __syncthreads();
    if (i < NN) {
        int excl = g_poff[blockIdx.x] + ws[wid] + x - v;
        g_rowptr[i] = excl;
        g_cursor[i] = excl;
    }
    if (blockIdx.x == 0 && threadIdx.x == 0) g_rowptr[NN] = NE;
}

__global__ void k_csr_fill(const int* __restrict__ src, const int* __restrict__ dst) {
    int e = blockIdx.x * blockDim.x + threadIdx.x;
    if (e < NE) {
        int pos = atomicAdd(&g_cursor[dst[e]], 1);
        g_csrc[pos] = src[e];
    }
}

// ---------------- gather SpMM + fused epilogues ----------------
__device__ __forceinline__ void acc_add(float4& a, const float4 b) {
    a.x += b.x; a.y += b.y; a.z += b.z; a.w += b.w;
}

// h = relu(in_norm * sum_{src in N(dst)} t[src] + b1)
__global__ void k_gather_h(const float* __restrict__ t, const float* __restrict__ b1,
                           float* __restrict__ h) {
    int node = (blockIdx.x * blockDim.x + threadIdx.x) >> 5;
    int lane = threadIdx.x & 31;
    if (node >= NN) return;
    int beg = g_rowptr[node], end = g_rowptr[node + 1];
    float4 a0 = make_float4(0.f, 0.f, 0.f, 0.f);
    float4 a1 = make_float4(0.f, 0.f, 0.f, 0.f);
    int j = beg;
    for (; j + 1 < end; j += 2) {
        int s0 = g_csrc[j], s1 = g_csrc[j + 1];
        const float4* r0 = (const float4*)(t + (size_t)s0 * DHID);
        const float4* r1 = (const float4*)(t + (size_t)s1 * DHID);
        float4 v00 = r0[lane], v01 = r0[lane + 32];
        float4 v10 = r1[lane], v11 = r1[lane + 32];
        acc_add(a0, v00); acc_add(a1, v01);
        acc_add(a0, v10); acc_add(a1, v11);
    }
    if (j < end) {
        const float4* r = (const float4*)(t + (size_t)g_csrc[j] * DHID);
        acc_add(a0, r[lane]); acc_add(a1, r[lane + 32]);
    }
    float s = g_innorm[node];
    float4 bb0 = ((const float4*)b1)[lane];
    float4 bb1 = ((const float4*)b1)[lane + 32];
    float4 o0, o1;
    o0.x = fmaxf(fmaf(a0.x, s, bb0.x), 0.f); o0.y = fmaxf(fmaf(a0.y, s, bb0.y), 0.f);
    o0.z = fmaxf(fmaf(a0.z, s, bb0.z), 0.f); o0.w = fmaxf(fmaf(a0.w, s, bb0.w), 0.f);
    o1.x = fmaxf(fmaf(a1.x, s, bb1.x), 0.f); o1.y = fmaxf(fmaf(a1.y, s, bb1.y), 0.f);
    o1.z = fmaxf(fmaf(a1.z, s, bb1.z), 0.f); o1.w = fmaxf(fmaf(a1.w, s, bb1.w), 0.f);
    float4* hp = (float4*)(h + (size_t)node * DHID);
    hp[lane] = o0;
    hp[lane + 32] = o1;
}

// z = relu(agg[:, :128]*in + b2) + noise * exp(agg[:, 128:]*in + b3)
__global__ void k_gather_z(const float* __restrict__ t, const float* __restrict__ b2,
                           const float* __restrict__ b3, const float* __restrict__ noise,
                           float* __restrict__ z) {
    int node = (blockIdx.x * blockDim.x + threadIdx.x) >> 5;
    int lane = threadIdx.x & 31;
    if (node >= NN) return;
    int beg = g_rowptr[node], end = g_rowptr[node + 1];
    float4 a0 = make_float4(0.f, 0.f, 0.f, 0.f);   // mean cols
    float4 a1 = make_float4(0.f, 0.f, 0.f, 0.f);   // logstd cols
    int j = beg;
    for (; j + 1 < end; j += 2) {
        int s0 = g_csrc[j], s1 = g_csrc[j + 1];
        const float4* r0 = (const float4*)(t + (size_t)s0 * DHID);
        const float4* r1 = (const float4*)(t + (size_t)s1 * DHID);
        float4 v00 = r0[lane], v01 = r0[lane + 32];
        float4 v10 = r1[lane], v11 = r1[lane + 32];
        acc_add(a0, v00); acc_add(a1, v01);
        acc_add(a0, v10); acc_add(a1, v11);
    }
    if (j < end) {
        const float4* r = (const float4*)(t + (size_t)g_csrc[j] * DHID);
        acc_add(a0, r[lane]); acc_add(a1, r[lane + 32]);
    }
    float s = g_innorm[node];
    float4 bm = ((const float4*)b2)[lane];
    float4 bl = ((const float4*)b3)[lane];
    float4 nv = ((const float4*)(noise + (size_t)node * DOUT))[lane];
    float4 r;
    r.x = fmaxf(fmaf(a0.x, s, bm.x), 0.f) + nv.x * expf(fmaf(a1.x, s, bl.x));
    r.y = fmaxf(fmaf(a0.y, s, bm.y), 0.f) + nv.y * expf(fmaf(a1.y, s, bl.y));
    r.z = fmaxf(fmaf(a0.z, s, bm.z), 0.f) + nv.z * expf(fmaf(a1.z, s, bl.z));
    r.w = fmaxf(fmaf(a0.w, s, bm.w), 0.f) + nv.w * expf(fmaf(a1.w, s, bl.w));
    ((float4*)(z + (size_t)node * DOUT))[lane] = r;
}

// ---------------- tf32 / cp.async helpers ----------------
__device__ __forceinline__ uint32_t f2tf32(float x) {
    uint32_t r;
    asm("cvt.rna.tf32.f32 %0, %1;" : "=r"(r) : "f"(x));
    return r;
}

__device__ __forceinline__ void mma_tf32(float* c, const uint32_t* a, const uint32_t* b) {
    asm volatile(
        "mma.sync.aligned.m16n8k8.row.col.f32.tf32.tf32.f32 "
        "{%0,%1,%2,%3}, {%4,%5,%6,%7}, {%8,%9}, {%0,%1,%2,%3};"
        : "+f"(c[0]), "+f"(c[1]), "+f"(c[2]), "+f"(c[3])
        : "r"(a[0]), "r"(a[1]), "r"(a[2]), "r"(a[3]), "r"(b[0]), "r"(b[1]));
}

__device__ __forceinline__ void cp16(uint32_t dst, const void* src) {
    asm volatile("cp.async.cg.shared.global [%0], [%1], 16;" :: "r"(dst), "l"(src));
}
__device__ __forceinline__ void cp_commit() { asm volatile("cp.async.commit_group;"); }
template<int N>
__device__ __forceinline__ void cp_wait() { asm volatile("cp.async.wait_group %0;" :: "n"(N)); }

// ---------------- tensor-core GEMM (cp.async double-buffered) ----------------
// C[M,Ncols] = (A @ B) * rowscale (applied to output rows; == (A*rowscale) @ B)
// TRANSB=0: B(k,n)=B[k*ld+n]; SPLITB: cols [0,128)->B0, [128,256)->B1 (ld=DOUT)
// TRANSB=1: B(k,n)=B0[n*K+k]
template<int TRANSB, int SPLITB>
__global__ void __launch_bounds__(256, 2)
k_gemm_mma(const float* __restrict__ A, const float* __restrict__ rowscale,
           const float* __restrict__ B0, const float* __restrict__ B1,
           float* __restrict__ C, int M, int Ncols, int K)
{
    constexpr int BM = 128, BN = 128, BK = 16;
    constexpr int ALD = BK + 4;                      // 20 floats/row, 16B-aligned stride
    constexpr int BSZ = TRANSB ? (BN * ALD) : (BK * (BN + 8));
    __shared__ float As[2][BM * ALD];
    __shared__ float Bs[2][BSZ];

    const int tid  = threadIdx.x;
    const int lane = tid & 31;
    const int warp = tid >> 5;
    const int row0 = blockIdx.y * BM;
    const int col0 = blockIdx.x * BN;
    const int warpM = (warp >> 2) * 64;
    const int warpN = (warp & 3) * 32;

    float acc[4][4][4];
#pragma unroll
    for (int i = 0; i < 4; i++)
#pragma unroll
        for (int j = 0; j < 4; j++)
#pragma unroll
            for (int r = 0; r < 4; r++) acc[i][j][r] = 0.f;

    const int ar = tid >> 2;          // row 0..63 (+64 on 2nd pass)
    const int ak4 = tid & 3;          // k quad
    const int bkr = tid >> 5;         // k row 0..7 (+8)
    const int bn4 = tid & 31;         // n quad

    const float* bbase;
    int bld = 0;
    if constexpr (TRANSB) {
        bbase = B0;                   // [Ncols][K]
    } else if constexpr (SPLITB) {
        bbase = (col0 == 0) ? B0 : B1;
        bld = DOUT;
    } else {
        bbase = B0 + col0;
        bld = Ncols;
    }

    auto stage = [&](int k0, int buf) {
#pragma unroll
        for (int i = 0; i < 2; i++) {
            int r = ar + i * 64;
            int gr = row0 + r;
            if (gr >= M) gr = M - 1;                  // clamp; OOB rows never stored
            cp16((uint32_t)__cvta_generic_to_shared(&As[buf][r * ALD + ak4 * 4]),
                 A + (size_t)gr * K + k0 + ak4 * 4);
        }
        if constexpr (TRANSB) {
#pragma unroll
            for (int i = 0; i < 2; i++) {
                int r = ar + i * 64;                  // n index
                cp16((uint32_t)__cvta_generic_to_shared(&Bs[buf][r * ALD + ak4 * 4]),
                     bbase + (size_t)(col0 + r) * K + k0 + ak4 * 4);
            }
        } else {
#pragma unroll
            for (int i = 0; i < 2; i++) {
                int k = bkr + i * 8;
                cp16((uint32_t)__cvta_generic_to_shared(&Bs[buf][k * (BN + 8) + bn4 * 4]),
                     bbase + (size_t)(k0 + k) * bld + bn4 * 4);
            }
        }
    };

    const int NT = K / BK;
    stage(0, 0);
    cp_commit();

    for (int t = 0; t < NT; t++) {
        int buf = t & 1;
        if (t + 1 < NT) {
            stage((t + 1) * BK, buf ^ 1);
            cp_commit();
            cp_wait<1>();
        } else {
            cp_wait<0>();
        }
        __syncthreads();

#pragma unroll
        for (int ks = 0; ks < 2; ks++) {
            uint32_t a[4][4], b[4][2];
#pragma unroll
            for (int mi = 0; mi < 4; mi++) {
                const float* ap = &As[buf][(warpM + mi * 16 + (lane >> 2)) * ALD + ks * 8 + (lane & 3)];
                a[mi][0] = f2tf32(ap[0]);
                a[mi][1] = f2tf32(ap[8 * ALD]);
                a[mi][2] = f2tf32(ap[4]);
                a[mi][3] = f2tf32(ap[8 * ALD + 4]);
            }
#pragma unroll
            for (int ni = 0; ni < 4; ni++) {
                if constexpr (TRANSB) {
                    const float* bp = &Bs[buf][(warpN + ni * 8 + (lane >> 2)) * ALD + ks * 8 + (lane & 3)];
                    b[ni][0] = f2tf32(bp[0]);
                    b[ni][1] = f2tf32(bp[4]);
                } else {
                    const float* bp = &Bs[buf][(ks * 8 + (lane & 3)) * (BN + 8) + warpN + ni * 8 + (lane >> 2)];
                    b[ni][0] = f2tf32(bp[0]);
                    b[ni][1] = f2tf32(bp[4 * (BN + 8)]);
                }
            }
#pragma unroll
            for (int mi = 0; mi < 4; mi++)
#pragma unroll
                for (int ni = 0; ni < 4; ni++)
                    mma_tf32(acc[mi][ni], a[mi], b[ni]);
        }
        __syncthreads();
    }

    // epilogue: apply rowscale to output rows, store fp32
#pragma unroll
    for (int mi = 0; mi < 4; mi++) {
        int gr0 = row0 + warpM + mi * 16 + (lane >> 2);
        float s0 = 1.f, s1 = 1.f;
        if (rowscale) {
            if (gr0 < M)     s0 = rowscale[gr0];
            if (gr0 + 8 < M) s1 = rowscale[gr0 + 8];
        }
#pragma unroll
        for (int ni = 0; ni < 4; ni++) {
            int col = col0 + warpN + ni * 8 + (lane & 3) * 2;
            if (gr0 < M)
                *(float2*)(C + (size_t)gr0 * Ncols + col) =
                    make_float2(acc[mi][ni][0] * s0, acc[mi][ni][1] * s0);
            if (gr0 + 8 < M)
                *(float2*)(C + (size_t)(gr0 + 8) * Ncols + col) =
                    make_float2(acc[mi][ni][2] * s1, acc[mi][ni][3] * s1);
        }
    }
}

// ---------------- launch ----------------
extern "C" void kernel_launch(void* const* d_in, const int* in_sizes, int n_in,
                              void* d_out, int out_size)
{
    const float* features = (const float*)d_in[0];
    const float* noise    = (const float*)d_in[1];
    const float* W1       = (const float*)d_in[2];
    const float* b1       = (const float*)d_in[3];
    const float* W2       = (const float*)d_in[4];
    const float* b2       = (const float*)d_in[5];
    const float* W3       = (const float*)d_in[6];
    const float* b3       = (const float*)d_in[7];
    const float* fcW      = (const float*)d_in[8];
    const int*   src      = (const int*)d_in[9];
    const int*   dst      = (const int*)d_in[10];

    float* out     = (float*)d_out;
    float* z_out   = out;                                 // [NN, 128]
    float* h_out   = out + (size_t)NN * DOUT;             // [NN, 256]
    float* seq_out = h_out + (size_t)NN * DHID;           // [NN, 256]

    float *pt, *pon;
    cudaGetSymbolAddress((void**)&pt,  g_t);
    cudaGetSymbolAddress((void**)&pon, g_outnorm);

    const int T = 256;
    // degrees, norms, CSR by dst
    k_zero_counts<<<(NN + T - 1) / T, T>>>();
    k_degree<<<(NE + T - 1) / T, T>>>(src, dst);
    k_fin_norms<<<(NN + T - 1) / T, T>>>();
    k_scan_p1<<<SCAN_GRID, SCAN_B>>>();
    k_scan_p2<<<1, SCAN_B>>>();
    k_scan_p3<<<SCAN_GRID, SCAN_B>>>();
    k_csr_fill<<<(NE + T - 1) / T, T>>>(src, dst);

    dim3 ggrid(2, (NN + 127) / 128);
    const int gather_blocks = (NN * 32 + T - 1) / T;

    // layer 1
    k_gemm_mma<0, 0><<<ggrid, T>>>(features, pon, W1, nullptr, pt, NN, DHID, DIN);
    k_gather_h<<<gather_blocks, T>>>(pt, b1, h_out);

    // layer 2 (W2|W3 fused)
    k_gemm_mma<0, 1><<<ggrid, T>>>(h_out, pon, W2, W3, pt, NN, DHID, DHID);
    k_gather_z<<<gather_blocks, T>>>(pt, b2, b3, noise, z_out);

    // seq_fts = features @ fcW^T
    k_gemm_mma<1, 0><<<ggrid, T>>>(features, nullptr, fcW, nullptr, seq_out, NN, DIN, DIN);
}

// round 8
// speedup vs baseline: 1.0421x; 1.0421x over previous
#include <cuda_runtime.h>
#include <cuda_bf16.h>
#include <cstdint>
#include <cstddef>

#define NN   50000
#define NE   800000
#define DIN  256
#define DHID 256
#define DOUT 128

#define SCAN_B 256
#define SCAN_GRID ((NN + SCAN_B - 1) / SCAN_B)   // 196

// ---------------- scratch (device globals; no allocation allowed) ----------------
__device__ float g_outnorm[NN];
__device__ float g_innorm[NN];
__device__ int   g_outc[NN];
__device__ int   g_inc[NN];
__device__ int   g_rowptr[NN + 1];
__device__ int   g_cursor[NN];
__device__ int   g_poff[SCAN_B];                     // block partial sums -> offsets
__device__ int   g_csrc[NE];                         // src node per CSR slot (by dst)
__device__ float g_t[(size_t)NN * DHID];             // layer-1 pre-agg features (fp32)
__device__ __nv_bfloat16 g_tb[(size_t)NN * DHID];    // layer-2 pre-agg features (bf16)

// ---------------- degree / norm / CSR kernels ----------------
__global__ void k_zero_counts() {
    int i = blockIdx.x * blockDim.x + threadIdx.x;
    if (i < NN) { g_outc[i] = 0; g_inc[i] = 0; }
}

__global__ void k_degree(const int* __restrict__ src, const int* __restrict__ dst) {
    int e = blockIdx.x * blockDim.x + threadIdx.x;
    if (e < NE) {
        atomicAdd(&g_outc[src[e]], 1);
        atomicAdd(&g_inc[dst[e]], 1);
    }
}

__global__ void k_fin_norms() {
    int i = blockIdx.x * blockDim.x + threadIdx.x;
    if (i < NN) {
        g_outnorm[i] = rsqrtf(fmaxf((float)g_outc[i], 1.f));
        g_innorm[i]  = rsqrtf(fmaxf((float)g_inc[i], 1.f));
    }
}

// ---- 3-phase multi-block exclusive scan of g_inc -> g_rowptr / g_cursor ----
__global__ void k_scan_p1() {
    __shared__ int ws[8];
    int i = blockIdx.x * SCAN_B + threadIdx.x;
    int lane = threadIdx.x & 31, wid = threadIdx.x >> 5;
    int v = (i < NN) ? g_inc[i] : 0;
#pragma unroll
    for (int o = 16; o > 0; o >>= 1) v += __shfl_down_sync(0xffffffffu, v, o);
    if (lane == 0) ws[wid] = v;
    __syncthreads();
    if (wid == 0) {
        int s = (lane < 8) ? ws[lane] : 0;
#pragma unroll
        for (int o = 4; o > 0; o >>= 1) s += __shfl_down_sync(0xffffffffu, s, o);
        if (lane == 0) g_poff[blockIdx.x] = s;
    }
}

__global__ void k_scan_p2() {
    __shared__ int ws[8];
    int tid = threadIdx.x, lane = tid & 31, wid = tid >> 5;
    int v = (tid < SCAN_GRID) ? g_poff[tid] : 0;
    int x = v;
#pragma unroll
    for (int o = 1; o < 32; o <<= 1) {
        int y = __shfl_up_sync(0xffffffffu, x, o);
        if (lane >= o) x += y;
    }
    if (lane == 31) ws[wid] = x;
    __syncthreads();
    if (wid == 0 && lane < 8) {
        int s = ws[lane];
        int xs = s;
#pragma unroll
        for (int o = 1; o < 8; o <<= 1) {
            int y = __shfl_up_sync(0xffu, xs, o);
            if (lane >= o) xs += y;
        }
        ws[lane] = xs - s;
    }
    __syncthreads();
    g_poff[tid] = ws[wid] + x - v;
}

__global__ void k_scan_p3() {
    __shared__ int ws[8];
    int i = blockIdx.x * SCAN_B + threadIdx.x;
    int lane = threadIdx.x & 31, wid = threadIdx.x >> 5;
    int v = (i < NN) ? g_inc[i] : 0;
    int x = v;
#pragma unroll
    for (int o = 1; o < 32; o <<= 1) {
        int y = __shfl_up_sync(0xffffffffu, x, o);
        if (lane >= o) x += y;
    }
    if (lane == 31) ws[wid] = x;
    __syncthreads();
    if (wid == 0 && lane < 8) {
        int s = ws[lane];
        int xs = s;
#pragma unroll
        for (int o = 1; o < 8; o <<= 1) {
            int y = __shfl_up_sync(0xffu, xs, o);
            if (lane >= o) xs += y;
        }
        ws[lane] = xs - s;
    }
    __syncthreads();
    if (i < NN) {
        int excl = g_poff[blockIdx.x] + ws[wid] + x - v;
        g_rowptr[i] = excl;
        g_cursor[i] = excl;
    }
    if (blockIdx.x == 0 && threadIdx.x == 0) g_rowptr[NN] = NE;
}

__global__ void k_csr_fill(const int* __restrict__ src, const int* __restrict__ dst) {
    int e = blockIdx.x * blockDim.x + threadIdx.x;
    if (e < NE) {
        int pos = atomicAdd(&g_cursor[dst[e]], 1);
        g_csrc[pos] = src[e];
    }
}

// ---------------- gather SpMM + fused epilogues ----------------
__device__ __forceinline__ void acc_add(float4& a, const float4 b) {
    a.x += b.x; a.y += b.y; a.z += b.z; a.w += b.w;
}

__device__ __forceinline__ void acc8_bf16(float* a, uint4 v) {
    __nv_bfloat162 p0 = *(__nv_bfloat162*)&v.x;
    __nv_bfloat162 p1 = *(__nv_bfloat162*)&v.y;
    __nv_bfloat162 p2 = *(__nv_bfloat162*)&v.z;
    __nv_bfloat162 p3 = *(__nv_bfloat162*)&v.w;
    float2 f0 = __bfloat1622float2(p0);
    float2 f1 = __bfloat1622float2(p1);
    float2 f2 = __bfloat1622float2(p2);
    float2 f3 = __bfloat1622float2(p3);
    a[0] += f0.x; a[1] += f0.y;
    a[2] += f1.x; a[3] += f1.y;
    a[4] += f2.x; a[5] += f2.y;
    a[6] += f3.x; a[7] += f3.y;
}

// h = relu(in_norm * sum_{src in N(dst)} t[src] + b1)   (t fp32)
__global__ void k_gather_h(const float* __restrict__ t, const float* __restrict__ b1,
                           float* __restrict__ h) {
    int node = (blockIdx.x * blockDim.x + threadIdx.x) >> 5;
    int lane = threadIdx.x & 31;
    if (node >= NN) return;
    int beg = g_rowptr[node], end = g_rowptr[node + 1];
    float4 a0 = make_float4(0.f, 0.f, 0.f, 0.f);
    float4 a1 = make_float4(0.f, 0.f, 0.f, 0.f);
    int j = beg;
    for (; j + 1 < end; j += 2) {
        int s0 = g_csrc[j], s1 = g_csrc[j + 1];
        const float4* r0 = (const float4*)(t + (size_t)s0 * DHID);
        const float4* r1 = (const float4*)(t + (size_t)s1 * DHID);
        float4 v00 = r0[lane], v01 = r0[lane + 32];
        float4 v10 = r1[lane], v11 = r1[lane + 32];
        acc_add(a0, v00); acc_add(a1, v01);
        acc_add(a0, v10); acc_add(a1, v11);
    }
    if (j < end) {
        const float4* r = (const float4*)(t + (size_t)g_csrc[j] * DHID);
        acc_add(a0, r[lane]); acc_add(a1, r[lane + 32]);
    }
    float s = g_innorm[node];
    float4 bb0 = ((const float4*)b1)[lane];
    float4 bb1 = ((const float4*)b1)[lane + 32];
    float4 o0, o1;
    o0.x = fmaxf(fmaf(a0.x, s, bb0.x), 0.f); o0.y = fmaxf(fmaf(a0.y, s, bb0.y), 0.f);
    o0.z = fmaxf(fmaf(a0.z, s, bb0.z), 0.f); o0.w = fmaxf(fmaf(a0.w, s, bb0.w), 0.f);
    o1.x = fmaxf(fmaf(a1.x, s, bb1.x), 0.f); o1.y = fmaxf(fmaf(a1.y, s, bb1.y), 0.f);
    o1.z = fmaxf(fmaf(a1.z, s, bb1.z), 0.f); o1.w = fmaxf(fmaf(a1.w, s, bb1.w), 0.f);
    float4* hp = (float4*)(h + (size_t)node * DHID);
    hp[lane] = o0;
    hp[lane + 32] = o1;
}

// z = relu(mean*in + b2) + noise * exp(logstd*in + b3)   (t bf16)
// lanes 0-15 accumulate mean cols (8 each), lanes 16-31 logstd cols.
__global__ void k_gather_z(const __nv_bfloat16* __restrict__ t,
                           const float* __restrict__ b2, const float* __restrict__ b3,
                           const float* __restrict__ noise, float* __restrict__ z) {
    int node = (blockIdx.x * blockDim.x + threadIdx.x) >> 5;
    int lane = threadIdx.x & 31;
    if (node >= NN) return;
    int beg = g_rowptr[node], end = g_rowptr[node + 1];
    float a[8];
#pragma unroll
    for (int i = 0; i < 8; i++) a[i] = 0.f;
    int j = beg;
    for (; j + 1 < end; j += 2) {
        int s0 = g_csrc[j], s1 = g_csrc[j + 1];
        uint4 v0 = ((const uint4*)(t + (size_t)s0 * DHID))[lane];
        uint4 v1 = ((const uint4*)(t + (size_t)s1 * DHID))[lane];
        acc8_bf16(a, v0);
        acc8_bf16(a, v1);
    }
    if (j < end) {
        uint4 v = ((const uint4*)(t + (size_t)g_csrc[j] * DHID))[lane];
        acc8_bf16(a, v);
    }
    // bring logstd accumulators (lanes 16-31) down to lanes 0-15
    float l[8];
#pragma unroll
    for (int i = 0; i < 8; i++) l[i] = __shfl_down_sync(0xffffffffu, a[i], 16);
    if (lane < 16) {
        float s = g_innorm[node];
        const float* bmp = b2 + lane * 8;
        const float* blp = b3 + lane * 8;
        const float* nvp = noise + (size_t)node * DOUT + lane * 8;
        float4 bm0 = *(const float4*)bmp,        bm1 = *(const float4*)(bmp + 4);
        float4 bl0 = *(const float4*)blp,        bl1 = *(const float4*)(blp + 4);
        float4 n0  = *(const float4*)nvp,        n1  = *(const float4*)(nvp + 4);
        float4 r0, r1;
        r0.x = fmaxf(fmaf(a[0], s, bm0.x), 0.f) + n0.x * expf(fmaf(l[0], s, bl0.x));
        r0.y = fmaxf(fmaf(a[1], s, bm0.y), 0.f) + n0.y * expf(fmaf(l[1], s, bl0.y));
        r0.z = fmaxf(fmaf(a[2], s, bm0.z), 0.f) + n0.z * expf(fmaf(l[2], s, bl0.z));
        r0.w = fmaxf(fmaf(a[3], s, bm0.w), 0.f) + n0.w * expf(fmaf(l[3], s, bl0.w));
        r1.x = fmaxf(fmaf(a[4], s, bm1.x), 0.f) + n1.x * expf(fmaf(l[4], s, bl1.x));
        r1.y = fmaxf(fmaf(a[5], s, bm1.y), 0.f) + n1.y * expf(fmaf(l[5], s, bl1.y));
        r1.z = fmaxf(fmaf(a[6], s, bm1.z), 0.f) + n1.z * expf(fmaf(l[6], s, bl1.z));
        r1.w = fmaxf(fmaf(a[7], s, bm1.w), 0.f) + n1.w * expf(fmaf(l[7], s, bl1.w));
        float* zp = z + (size_t)node * DOUT + lane * 8;
        *(float4*)zp = r0;
        *(float4*)(zp + 4) = r1;
    }
}

// ---------------- tf32 / cp.async helpers ----------------
__device__ __forceinline__ uint32_t f2tf32(float x) {
    uint32_t r;
    asm("cvt.rna.tf32.f32 %0, %1;" : "=r"(r) : "f"(x));
    return r;
}

__device__ __forceinline__ void mma_tf32(float* c, const uint32_t* a, const uint32_t* b) {
    asm volatile(
        "mma.sync.aligned.m16n8k8.row.col.f32.tf32.tf32.f32 "
        "{%0,%1,%2,%3}, {%4,%5,%6,%7}, {%8,%9}, {%0,%1,%2,%3};"
        : "+f"(c[0]), "+f"(c[1]), "+f"(c[2]), "+f"(c[3])
        : "r"(a[0]), "r"(a[1]), "r"(a[2]), "r"(a[3]), "r"(b[0]), "r"(b[1]));
}

__device__ __forceinline__ void cp16(uint32_t dst, const void* src) {
    asm volatile("cp.async.cg.shared.global [%0], [%1], 16;" :: "r"(dst), "l"(src));
}
__device__ __forceinline__ void cp_commit() { asm volatile("cp.async.commit_group;"); }
template<int N>
__device__ __forceinline__ void cp_wait() { asm volatile("cp.async.wait_group %0;" :: "n"(N)); }

// ---------------- tensor-core GEMM (cp.async double-buffered) ----------------
// C[M,Ncols] = (A @ B) * rowscale (applied to output rows)
// TRANSB=0: B(k,n)=B[k*ld+n]; SPLITB: cols [0,128)->B0, [128,256)->B1 (ld=DOUT)
// TRANSB=1: B(k,n)=B0[n*K+k]
// OUTBF16=1: C is __nv_bfloat16* (packed bf16x2 stores); else float*.
template<int TRANSB, int SPLITB, int OUTBF16>
__global__ void __launch_bounds__(256, 2)
k_gemm_mma(const float* __restrict__ A, const float* __restrict__ rowscale,
           const float* __restrict__ B0, const float* __restrict__ B1,
           void* __restrict__ Cv, int M, int Ncols, int K)
{
    constexpr int BM = 128, BN = 128, BK = 16;
    constexpr int ALD = BK + 4;
    constexpr int BSZ = TRANSB ? (BN * ALD) : (BK * (BN + 8));
    __shared__ float As[2][BM * ALD];
    __shared__ float Bs[2][BSZ];

    const int tid  = threadIdx.x;
    const int lane = tid & 31;
    const int warp = tid >> 5;
    const int row0 = blockIdx.y * BM;
    const int col0 = blockIdx.x * BN;
    const int warpM = (warp >> 2) * 64;
    const int warpN = (warp & 3) * 32;

    float acc[4][4][4];
#pragma unroll
    for (int i = 0; i < 4; i++)
#pragma unroll
        for (int j = 0; j < 4; j++)
#pragma unroll
            for (int r = 0; r < 4; r++) acc[i][j][r] = 0.f;

    const int ar = tid >> 2;
    const int ak4 = tid & 3;
    const int bkr = tid >> 5;
    const int bn4 = tid & 31;

    const float* bbase;
    int bld = 0;
    if constexpr (TRANSB) {
        bbase = B0;
    } else if constexpr (SPLITB) {
        bbase = (col0 == 0) ? B0 : B1;
        bld = DOUT;
    } else {
        bbase = B0 + col0;
        bld = Ncols;
    }

    auto stage = [&](int k0, int buf) {
#pragma unroll
        for (int i = 0; i < 2; i++) {
            int r = ar + i * 64;
            int gr = row0 + r;
            if (gr >= M) gr = M - 1;
            cp16((uint32_t)__cvta_generic_to_shared(&As[buf][r * ALD + ak4 * 4]),
                 A + (size_t)gr * K + k0 + ak4 * 4);
        }
        if constexpr (TRANSB) {
#pragma unroll
            for (int i = 0; i < 2; i++) {
                int r = ar + i * 64;
                cp16((uint32_t)__cvta_generic_to_shared(&Bs[buf][r * ALD + ak4 * 4]),
                     bbase + (size_t)(col0 + r) * K + k0 + ak4 * 4);
            }
        } else {
#pragma unroll
            for (int i = 0; i < 2; i++) {
                int k = bkr + i * 8;
                cp16((uint32_t)__cvta_generic_to_shared(&Bs[buf][k * (BN + 8) + bn4 * 4]),
                     bbase + (size_t)(k0 + k) * bld + bn4 * 4);
            }
        }
    };

    const int NT = K / BK;
    stage(0, 0);
    cp_commit();

    for (int t = 0; t < NT; t++) {
        int buf = t & 1;
        if (t + 1 < NT) {
            stage((t + 1) * BK, buf ^ 1);
            cp_commit();
            cp_wait<1>();
        } else {
            cp_wait<0>();
        }
        __syncthreads();

#pragma unroll
        for (int ks = 0; ks < 2; ks++) {
            uint32_t a[4][4], b[4][2];
#pragma unroll
            for (int mi = 0; mi < 4; mi++) {
                const float* ap = &As[buf][(warpM + mi * 16 + (lane >> 2)) * ALD + ks * 8 + (lane & 3)];
                a[mi][0] = f2tf32(ap[0]);
                a[mi][1] = f2tf32(ap[8 * ALD]);
                a[mi][2] = f2tf32(ap[4]);
                a[mi][3] = f2tf32(ap[8 * ALD + 4]);
            }
#pragma unroll
            for (int ni = 0; ni < 4; ni++) {
                if constexpr (TRANSB) {
                    const float* bp = &Bs[buf][(warpN + ni * 8 + (lane >> 2)) * ALD + ks * 8 + (lane & 3)];
                    b[ni][0] = f2tf32(bp[0]);
                    b[ni][1] = f2tf32(bp[4]);
                } else {
                    const float* bp = &Bs[buf][(ks * 8 + (lane & 3)) * (BN + 8) + warpN + ni * 8 + (lane >> 2)];
                    b[ni][0] = f2tf32(bp[0]);
                    b[ni][1] = f2tf32(bp[4 * (BN + 8)]);
                }
            }
#pragma unroll
            for (int mi = 0; mi < 4; mi++)
#pragma unroll
                for (int ni = 0; ni < 4; ni++)
                    mma_tf32(acc[mi][ni], a[mi], b[ni]);
        }
        __syncthreads();
    }

    // epilogue: rowscale + store (fp32 or packed bf16x2)
#pragma unroll
    for (int mi = 0; mi < 4; mi++) {
        int gr0 = row0 + warpM + mi * 16 + (lane >> 2);
        float s0 = 1.f, s1 = 1.f;
        if (rowscale) {
            if (gr0 < M)     s0 = rowscale[gr0];
            if (gr0 + 8 < M) s1 = rowscale[gr0 + 8];
        }
#pragma unroll
        for (int ni = 0; ni < 4; ni++) {
            int col = col0 + warpN + ni * 8 + (lane & 3) * 2;
            if constexpr (OUTBF16) {
                __nv_bfloat16* Cb = (__nv_bfloat16*)Cv;
                if (gr0 < M)
                    *(__nv_bfloat162*)(Cb + (size_t)gr0 * Ncols + col) =
                        __float22bfloat162_rn(make_float2(acc[mi][ni][0] * s0, acc[mi][ni][1] * s0));
                if (gr0 + 8 < M)
                    *(__nv_bfloat162*)(Cb + (size_t)(gr0 + 8) * Ncols + col) =
                        __float22bfloat162_rn(make_float2(acc[mi][ni][2] * s1, acc[mi][ni][3] * s1));
            } else {
                float* C = (float*)Cv;
                if (gr0 < M)
                    *(float2*)(C + (size_t)gr0 * Ncols + col) =
                        make_float2(acc[mi][ni][0] * s0, acc[mi][ni][1] * s0);
                if (gr0 + 8 < M)
                    *(float2*)(C + (size_t)(gr0 + 8) * Ncols + col) =
                        make_float2(acc[mi][ni][2] * s1, acc[mi][ni][3] * s1);
            }
        }
    }
}

// ---------------- launch ----------------
extern "C" void kernel_launch(void* const* d_in, const int* in_sizes, int n_in,
                              void* d_out, int out_size)
{
    const float* features = (const float*)d_in[0];
    const float* noise    = (const float*)d_in[1];
    const float* W1       = (const float*)d_in[2];
    const float* b1       = (const float*)d_in[3];
    const float* W2       = (const float*)d_in[4];
    const float* b2       = (const float*)d_in[5];
    const float* W3       = (const float*)d_in[6];
    const float* b3       = (const float*)d_in[7];
    const float* fcW      = (const float*)d_in[8];
    const int*   src      = (const int*)d_in[9];
    const int*   dst      = (const int*)d_in[10];

    float* out     = (float*)d_out;
    float* z_out   = out;                                 // [NN, 128]
    float* h_out   = out + (size_t)NN * DOUT;             // [NN, 256]
    float* seq_out = h_out + (size_t)NN * DHID;           // [NN, 256]

    float *pt, *pon;
    __nv_bfloat16 *ptb;
    cudaGetSymbolAddress((void**)&pt,  g_t);
    cudaGetSymbolAddress((void**)&ptb, g_tb);
    cudaGetSymbolAddress((void**)&pon, g_outnorm);

    const int T = 256;
    // degrees, norms, CSR by dst
    k_zero_counts<<<(NN + T - 1) / T, T>>>();
    k_degree<<<(NE + T - 1) / T, T>>>(src, dst);
    k_fin_norms<<<(NN + T - 1) / T, T>>>();
    k_scan_p1<<<SCAN_GRID, SCAN_B>>>();
    k_scan_p2<<<1, SCAN_B>>>();
    k_scan_p3<<<SCAN_GRID, SCAN_B>>>();
    k_csr_fill<<<(NE + T - 1) / T, T>>>(src, dst);

    dim3 ggrid(2, (NN + 127) / 128);
    const int gather_blocks = (NN * 32 + T - 1) / T;

    // layer 1 (fp32 t -> accurate h): t = (features @ W1) * outnorm ; h = gather+relu
    k_gemm_mma<0, 0, 0><<<ggrid, T>>>(features, pon, W1, nullptr, pt, NN, DHID, DIN);
    k_gather_h<<<gather_blocks, T>>>(pt, b1, h_out);

    // layer 2 (bf16 t -> z has slack): t = (h @ [W2|W3]) * outnorm ; z = gather+reparam
    k_gemm_mma<0, 1, 1><<<ggrid, T>>>(h_out, pon, W2, W3, ptb, NN, DHID, DHID);
    k_gather_z<<<gather_blocks, T>>>(ptb, b2, b3, noise, z_out);

    // seq_fts = features @ fcW^T (fp32 output)
    k_gemm_mma<1, 0, 0><<<ggrid, T>>>(features, nullptr, fcW, nullptr, seq_out, NN, DIN, DIN);
}

// round 9
// speedup vs baseline: 1.1303x; 1.0847x over previous
#include <cuda_runtime.h>
#include <cuda_fp16.h>
#include <cstdint>
#include <cstddef>

#define NN   50000
#define NE   800000
#define DIN  256
#define DHID 256
#define DOUT 128

#define SCAN_B 256
#define SCAN_GRID ((NN + SCAN_B - 1) / SCAN_B)   // 196

// ---------------- scratch (device globals; no allocation allowed) ----------------
__device__ float g_outnorm[NN];
__device__ float g_innorm[NN];
__device__ int   g_outc[NN];
__device__ int   g_inc[NN];
__device__ int   g_rowptr[NN + 1];
__device__ int   g_cursor[NN];
__device__ int   g_poff[SCAN_B];                 // block partial sums -> offsets
__device__ int   g_csrc[NE];                     // src node per CSR slot (by dst)
__device__ __half g_th[(size_t)NN * DHID];       // pre-agg features (fp16, both layers)

// ---------------- degree / norm / CSR kernels ----------------
__global__ void k_zero_counts() {
    int i = blockIdx.x * blockDim.x + threadIdx.x;
    if (i < NN) { g_outc[i] = 0; g_inc[i] = 0; }
}

__global__ void k_degree(const int* __restrict__ src, const int* __restrict__ dst) {
    int e = blockIdx.x * blockDim.x + threadIdx.x;
    if (e < NE) {
        atomicAdd(&g_outc[src[e]], 1);
        atomicAdd(&g_inc[dst[e]], 1);
    }
}

__global__ void k_fin_norms() {
    int i = blockIdx.x * blockDim.x + threadIdx.x;
    if (i < NN) {
        g_outnorm[i] = rsqrtf(fmaxf((float)g_outc[i], 1.f));
        g_innorm[i]  = rsqrtf(fmaxf((float)g_inc[i], 1.f));
    }
}

// ---- 3-phase multi-block exclusive scan of g_inc -> g_rowptr / g_cursor ----
__global__ void k_scan_p1() {
    __shared__ int ws[8];
    int i = blockIdx.x * SCAN_B + threadIdx.x;
    int lane = threadIdx.x & 31, wid = threadIdx.x >> 5;
    int v = (i < NN) ? g_inc[i] : 0;
#pragma unroll
    for (int o = 16; o > 0; o >>= 1) v += __shfl_down_sync(0xffffffffu, v, o);
    if (lane == 0) ws[wid] = v;
    __syncthreads();
    if (wid == 0) {
        int s = (lane < 8) ? ws[lane] : 0;
#pragma unroll
        for (int o = 4; o > 0; o >>= 1) s += __shfl_down_sync(0xffffffffu, s, o);
        if (lane == 0) g_poff[blockIdx.x] = s;
    }
}

__global__ void k_scan_p2() {
    __shared__ int ws[8];
    int tid = threadIdx.x, lane = tid & 31, wid = tid >> 5;
    int v = (tid < SCAN_GRID) ? g_poff[tid] : 0;
    int x = v;
#pragma unroll
    for (int o = 1; o < 32; o <<= 1) {
        int y = __shfl_up_sync(0xffffffffu, x, o);
        if (lane >= o) x += y;
    }
    if (lane == 31) ws[wid] = x;
    __syncthreads();
    if (wid == 0 && lane < 8) {
        int s = ws[lane];
        int xs = s;
#pragma unroll
        for (int o = 1; o < 8; o <<= 1) {
            int y = __shfl_up_sync(0xffu, xs, o);
            if (lane >= o) xs += y;
        }
        ws[lane] = xs - s;
    }
    __syncthreads();
    g_poff[tid] = ws[wid] + x - v;
}

__global__ void k_scan_p3() {
    __shared__ int ws[8];
    int i = blockIdx.x * SCAN_B + threadIdx.x;
    int lane = threadIdx.x & 31, wid = threadIdx.x >> 5;
    int v = (i < NN) ? g_inc[i] : 0;
    int x = v;
#pragma unroll
    for (int o = 1; o < 32; o <<= 1) {
        int y = __shfl_up_sync(0xffffffffu, x, o);
        if (lane >= o) x += y;
    }
    if (lane == 31) ws[wid] = x;
    __syncthreads();
    if (wid == 0 && lane < 8) {
        int s = ws[lane];
        int xs = s;
#pragma unroll
        for (int o = 1; o < 8; o <<= 1) {
            int y = __shfl_up_sync(0xffu, xs, o);
            if (lane >= o) xs += y;
        }
        ws[lane] = xs - s;
    }
    __syncthreads();
    if (i < NN) {
        int excl = g_poff[blockIdx.x] + ws[wid] + x - v;
        g_rowptr[i] = excl;
        g_cursor[i] = excl;
    }
    if (blockIdx.x == 0 && threadIdx.x == 0) g_rowptr[NN] = NE;
}

__global__ void k_csr_fill(const int* __restrict__ src, const int* __restrict__ dst) {
    int e = blockIdx.x * blockDim.x + threadIdx.x;
    if (e < NE) {
        int pos = atomicAdd(&g_cursor[dst[e]], 1);
        g_csrc[pos] = src[e];
    }
}

// ---------------- fp16 gather SpMM + fused epilogues ----------------
// a[0..7] += s * (8 halfs of v)
__device__ __forceinline__ void acc8_f16(float* a, uint4 v, float s) {
    __half2 p0 = *(__half2*)&v.x;
    __half2 p1 = *(__half2*)&v.y;
    __half2 p2 = *(__half2*)&v.z;
    __half2 p3 = *(__half2*)&v.w;
    float2 f0 = __half22float2(p0);
    float2 f1 = __half22float2(p1);
    float2 f2 = __half22float2(p2);
    float2 f3 = __half22float2(p3);
    a[0] = fmaf(f0.x, s, a[0]); a[1] = fmaf(f0.y, s, a[1]);
    a[2] = fmaf(f1.x, s, a[2]); a[3] = fmaf(f1.y, s, a[3]);
    a[4] = fmaf(f2.x, s, a[4]); a[5] = fmaf(f2.y, s, a[5]);
    a[6] = fmaf(f3.x, s, a[6]); a[7] = fmaf(f3.y, s, a[7]);
}

// h = relu(in_norm * sum_{src in N(dst)} outnorm[src]*t[src] + b1)   (t fp16 UNSCALED)
__global__ void k_gather_h(const __half* __restrict__ t, const float* __restrict__ b1,
                           float* __restrict__ h) {
    int node = (blockIdx.x * blockDim.x + threadIdx.x) >> 5;
    int lane = threadIdx.x & 31;
    if (node >= NN) return;
    int beg = g_rowptr[node], end = g_rowptr[node + 1];
    float a[8];
#pragma unroll
    for (int i = 0; i < 8; i++) a[i] = 0.f;
    int j = beg;
    for (; j + 1 < end; j += 2) {
        int s0 = g_csrc[j], s1 = g_csrc[j + 1];
        float on0 = g_outnorm[s0], on1 = g_outnorm[s1];
        uint4 v0 = ((const uint4*)(t + (size_t)s0 * DHID))[lane];
        uint4 v1 = ((const uint4*)(t + (size_t)s1 * DHID))[lane];
        acc8_f16(a, v0, on0);
        acc8_f16(a, v1, on1);
    }
    if (j < end) {
        int s0 = g_csrc[j];
        float on0 = g_outnorm[s0];
        uint4 v = ((const uint4*)(t + (size_t)s0 * DHID))[lane];
        acc8_f16(a, v, on0);
    }
    float s = g_innorm[node];
    const float* bp = b1 + lane * 8;
    float4 bb0 = *(const float4*)bp;
    float4 bb1 = *(const float4*)(bp + 4);
    float4 o0, o1;
    o0.x = fmaxf(fmaf(a[0], s, bb0.x), 0.f); o0.y = fmaxf(fmaf(a[1], s, bb0.y), 0.f);
    o0.z = fmaxf(fmaf(a[2], s, bb0.z), 0.f); o0.w = fmaxf(fmaf(a[3], s, bb0.w), 0.f);
    o1.x = fmaxf(fmaf(a[4], s, bb1.x), 0.f); o1.y = fmaxf(fmaf(a[5], s, bb1.y), 0.f);
    o1.z = fmaxf(fmaf(a[6], s, bb1.z), 0.f); o1.w = fmaxf(fmaf(a[7], s, bb1.w), 0.f);
    float* hp = h + (size_t)node * DHID + lane * 8;
    *(float4*)hp = o0;
    *(float4*)(hp + 4) = o1;
}

// z = relu(mean*in + b2) + noise * exp(logstd*in + b3)   (t fp16, pre-scaled by outnorm)
// lanes 0-15 accumulate mean cols (8 each), lanes 16-31 logstd cols.
__global__ void k_gather_z(const __half* __restrict__ t,
                           const float* __restrict__ b2, const float* __restrict__ b3,
                           const float* __restrict__ noise, float* __restrict__ z) {
    int node = (blockIdx.x * blockDim.x + threadIdx.x) >> 5;
    int lane = threadIdx.x & 31;
    if (node >= NN) return;
    int beg = g_rowptr[node], end = g_rowptr[node + 1];
    float a[8];
#pragma unroll
    for (int i = 0; i < 8; i++) a[i] = 0.f;
    int j = beg;
    for (; j + 1 < end; j += 2) {
        int s0 = g_csrc[j], s1 = g_csrc[j + 1];
        uint4 v0 = ((const uint4*)(t + (size_t)s0 * DHID))[lane];
        uint4 v1 = ((const uint4*)(t + (size_t)s1 * DHID))[lane];
        acc8_f16(a, v0, 1.f);
        acc8_f16(a, v1, 1.f);
    }
    if (j < end) {
        uint4 v = ((const uint4*)(t + (size_t)g_csrc[j] * DHID))[lane];
        acc8_f16(a, v, 1.f);
    }
    // bring logstd accumulators (lanes 16-31) down to lanes 0-15
    float l[8];
#pragma unroll
    for (int i = 0; i < 8; i++) l[i] = __shfl_down_sync(0xffffffffu, a[i], 16);
    if (lane < 16) {
        float s = g_innorm[node];
        const float* bmp = b2 + lane * 8;
        const float* blp = b3 + lane * 8;
        const float* nvp = noise + (size_t)node * DOUT + lane * 8;
        float4 bm0 = *(const float4*)bmp,        bm1 = *(const float4*)(bmp + 4);
        float4 bl0 = *(const float4*)blp,        bl1 = *(const float4*)(blp + 4);
        float4 n0  = *(const float4*)nvp,        n1  = *(const float4*)(nvp + 4);
        float4 r0, r1;
        r0.x = fmaxf(fmaf(a[0], s, bm0.x), 0.f) + n0.x * expf(fmaf(l[0], s, bl0.x));
        r0.y = fmaxf(fmaf(a[1], s, bm0.y), 0.f) + n0.y * expf(fmaf(l[1], s, bl0.y));
        r0.z = fmaxf(fmaf(a[2], s, bm0.z), 0.f) + n0.z * expf(fmaf(l[2], s, bl0.z));
        r0.w = fmaxf(fmaf(a[3], s, bm0.w), 0.f) + n0.w * expf(fmaf(l[3], s, bl0.w));
        r1.x = fmaxf(fmaf(a[4], s, bm1.x), 0.f) + n1.x * expf(fmaf(l[4], s, bl1.x));
        r1.y = fmaxf(fmaf(a[5], s, bm1.y), 0.f) + n1.y * expf(fmaf(l[5], s, bl1.y));
        r1.z = fmaxf(fmaf(a[6], s, bm1.z), 0.f) + n1.z * expf(fmaf(l[6], s, bl1.z));
        r1.w = fmaxf(fmaf(a[7], s, bm1.w), 0.f) + n1.w * expf(fmaf(l[7], s, bl1.w));
        float* zp = z + (size_t)node * DOUT + lane * 8;
        *(float4*)zp = r0;
        *(float4*)(zp + 4) = r1;
    }
}

// ---------------- tf32 / cp.async helpers ----------------
__device__ __forceinline__ uint32_t f2tf32(float x) {
    uint32_t r;
    asm("cvt.rna.tf32.f32 %0, %1;" : "=r"(r) : "f"(x));
    return r;
}

__device__ __forceinline__ void mma_tf32(float* c, const uint32_t* a, const uint32_t* b) {
    asm volatile(
        "mma.sync.aligned.m16n8k8.row.col.f32.tf32.tf32.f32 "
        "{%0,%1,%2,%3}, {%4,%5,%6,%7}, {%8,%9}, {%0,%1,%2,%3};"
        : "+f"(c[0]), "+f"(c[1]), "+f"(c[2]), "+f"(c[3])
        : "r"(a[0]), "r"(a[1]), "r"(a[2]), "r"(a[3]), "r"(b[0]), "r"(b[1]));
}

__device__ __forceinline__ void cp16(uint32_t dst, const void* src) {
    asm volatile("cp.async.cg.shared.global [%0], [%1], 16;" :: "r"(dst), "l"(src));
}
__device__ __forceinline__ void cp_commit() { asm volatile("cp.async.commit_group;"); }
template<int N>
__device__ __forceinline__ void cp_wait() { asm volatile("cp.async.wait_group %0;" :: "n"(N)); }

// ---------------- tensor-core GEMM (cp.async double-buffered) ----------------
// C[M,Ncols] = (A @ B) * rowscale (applied to output rows)
// TRANSB=0: B(k,n)=B[k*ld+n]; SPLITB: cols [0,128)->B0, [128,256)->B1 (ld=DOUT)
// TRANSB=1: B(k,n)=B0[n*K+k]
// OUTHALF=1: C is __half* (packed half2 stores); else float*.
template<int TRANSB, int SPLITB, int OUTHALF>
__global__ void __launch_bounds__(256, 2)
k_gemm_mma(const float* __restrict__ A, const float* __restrict__ rowscale,
           const float* __restrict__ B0, const float* __restrict__ B1,
           void* __restrict__ Cv, int M, int Ncols, int K)
{
    constexpr int BM = 128, BN = 128, BK = 16;
    constexpr int ALD = BK + 4;
    constexpr int BSZ = TRANSB ? (BN * ALD) : (BK * (BN + 8));
    __shared__ float As[2][BM * ALD];
    __shared__ float Bs[2][BSZ];

    const int tid  = threadIdx.x;
    const int lane = tid & 31;
    const int warp = tid >> 5;
    const int row0 = blockIdx.y * BM;
    const int col0 = blockIdx.x * BN;
    const int warpM = (warp >> 2) * 64;
    const int warpN = (warp & 3) * 32;

    float acc[4][4][4];
#pragma unroll
    for (int i = 0; i < 4; i++)
#pragma unroll
        for (int j = 0; j < 4; j++)
#pragma unroll
            for (int r = 0; r < 4; r++) acc[i][j][r] = 0.f;

    const int ar = tid >> 2;
    const int ak4 = tid & 3;
    const int bkr = tid >> 5;
    const int bn4 = tid & 31;

    const float* bbase;
    int bld = 0;
    if constexpr (TRANSB) {
        bbase = B0;
    } else if constexpr (SPLITB) {
        bbase = (col0 == 0) ? B0 : B1;
        bld = DOUT;
    } else {
        bbase = B0 + col0;
        bld = Ncols;
    }

    auto stage = [&](int k0, int buf) {
#pragma unroll
        for (int i = 0; i < 2; i++) {
            int r = ar + i * 64;
            int gr = row0 + r;
            if (gr >= M) gr = M - 1;
            cp16((uint32_t)__cvta_generic_to_shared(&As[buf][r * ALD + ak4 * 4]),
                 A + (size_t)gr * K + k0 + ak4 * 4);
        }
        if constexpr (TRANSB) {
#pragma unroll
            for (int i = 0; i < 2; i++) {
                int r = ar + i * 64;
                cp16((uint32_t)__cvta_generic_to_shared(&Bs[buf][r * ALD + ak4 * 4]),
                     bbase + (size_t)(col0 + r) * K + k0 + ak4 * 4);
            }
        } else {
#pragma unroll
            for (int i = 0; i < 2; i++) {
                int k = bkr + i * 8;
                cp16((uint32_t)__cvta_generic_to_shared(&Bs[buf][k * (BN + 8) + bn4 * 4]),
                     bbase + (size_t)(k0 + k) * bld + bn4 * 4);
            }
        }
    };

    const int NT = K / BK;
    stage(0, 0);
    cp_commit();

    for (int t = 0; t < NT; t++) {
        int buf = t & 1;
        if (t + 1 < NT) {
            stage((t + 1) * BK, buf ^ 1);
            cp_commit();
            cp_wait<1>();
        } else {
            cp_wait<0>();
        }
        __syncthreads();

#pragma unroll
        for (int ks = 0; ks < 2; ks++) {
            uint32_t a[4][4], b[4][2];
#pragma unroll
            for (int mi = 0; mi < 4; mi++) {
                const float* ap = &As[buf][(warpM + mi * 16 + (lane >> 2)) * ALD + ks * 8 + (lane & 3)];
                a[mi][0] = f2tf32(ap[0]);
                a[mi][1] = f2tf32(ap[8 * ALD]);
                a[mi][2] = f2tf32(ap[4]);
                a[mi][3] = f2tf32(ap[8 * ALD + 4]);
            }
#pragma unroll
            for (int ni = 0; ni < 4; ni++) {
                if constexpr (TRANSB) {
                    const float* bp = &Bs[buf][(warpN + ni * 8 + (lane >> 2)) * ALD + ks * 8 + (lane & 3)];
                    b[ni][0] = f2tf32(bp[0]);
                    b[ni][1] = f2tf32(bp[4]);
                } else {
                    const float* bp = &Bs[buf][(ks * 8 + (lane & 3)) * (BN + 8) + warpN + ni * 8 + (lane >> 2)];
                    b[ni][0] = f2tf32(bp[0]);
                    b[ni][1] = f2tf32(bp[4 * (BN + 8)]);
                }
            }
#pragma unroll
            for (int mi = 0; mi < 4; mi++)
#pragma unroll
                for (int ni = 0; ni < 4; ni++)
                    mma_tf32(acc[mi][ni], a[mi], b[ni]);
        }
        __syncthreads();
    }

    // epilogue: rowscale + store (fp32 or packed half2)
#pragma unroll
    for (int mi = 0; mi < 4; mi++) {
        int gr0 = row0 + warpM + mi * 16 + (lane >> 2);
        float s0 = 1.f, s1 = 1.f;
        if (rowscale) {
            if (gr0 < M)     s0 = rowscale[gr0];
            if (gr0 + 8 < M) s1 = rowscale[gr0 + 8];
        }
#pragma unroll
        for (int ni = 0; ni < 4; ni++) {
            int col = col0 + warpN + ni * 8 + (lane & 3) * 2;
            if constexpr (OUTHALF) {
                __half* Ch = (__half*)Cv;
                if (gr0 < M)
                    *(__half2*)(Ch + (size_t)gr0 * Ncols + col) =
                        __float22half2_rn(make_float2(acc[mi][ni][0] * s0, acc[mi][ni][1] * s0));
                if (gr0 + 8 < M)
                    *(__half2*)(Ch + (size_t)(gr0 + 8) * Ncols + col) =
                        __float22half2_rn(make_float2(acc[mi][ni][2] * s1, acc[mi][ni][3] * s1));
            } else {
                float* C = (float*)Cv;
                if (gr0 < M)
                    *(float2*)(C + (size_t)gr0 * Ncols + col) =
                        make_float2(acc[mi][ni][0] * s0, acc[mi][ni][1] * s0);
                if (gr0 + 8 < M)
                    *(float2*)(C + (size_t)(gr0 + 8) * Ncols + col) =
                        make_float2(acc[mi][ni][2] * s1, acc[mi][ni][3] * s1);
            }
        }
    }
}

// ---------------- stream/event singletons (host resources, created once) ----------
namespace {
struct HxRes {
    cudaStream_t s_pre = nullptr;
    cudaEvent_t  e_fork = nullptr, e_csr = nullptr;
    HxRes() {
        cudaStreamCreateWithFlags(&s_pre, cudaStreamNonBlocking);
        cudaEventCreateWithFlags(&e_fork, cudaEventDisableTiming);
        cudaEventCreateWithFlags(&e_csr,  cudaEventDisableTiming);
    }
};
HxRes g_res;
}

// ---------------- launch ----------------
extern "C" void kernel_launch(void* const* d_in, const int* in_sizes, int n_in,
                              void* d_out, int out_size)
{
    const float* features = (const float*)d_in[0];
    const float* noise    = (const float*)d_in[1];
    const float* W1       = (const float*)d_in[2];
    const float* b1       = (const float*)d_in[3];
    const float* W2       = (const float*)d_in[4];
    const float* b2       = (const float*)d_in[5];
    const float* W3       = (const float*)d_in[6];
    const float* b3       = (const float*)d_in[7];
    const float* fcW      = (const float*)d_in[8];
    const int*   src      = (const int*)d_in[9];
    const int*   dst      = (const int*)d_in[10];

    float* out     = (float*)d_out;
    float* z_out   = out;                                 // [NN, 128]
    float* h_out   = out + (size_t)NN * DOUT;             // [NN, 256]
    float* seq_out = h_out + (size_t)NN * DHID;           // [NN, 256]

    __half* pth;
    float*  pon;
    cudaGetSymbolAddress((void**)&pth, g_th);
    cudaGetSymbolAddress((void**)&pon, g_outnorm);

    const int T = 256;
    dim3 ggrid(2, (NN + 127) / 128);
    const int gather_blocks = (NN * 32 + T - 1) / T;

    // ---- fork: CSR prologue on side stream (independent of gemm1/gemm3) ----
    cudaEventRecord(g_res.e_fork, 0);
    cudaStreamWaitEvent(g_res.s_pre, g_res.e_fork, 0);
    k_zero_counts<<<(NN + T - 1) / T, T, 0, g_res.s_pre>>>();
    k_degree<<<(NE + T - 1) / T, T, 0, g_res.s_pre>>>(src, dst);
    k_fin_norms<<<(NN + T - 1) / T, T, 0, g_res.s_pre>>>();
    k_scan_p1<<<SCAN_GRID, SCAN_B, 0, g_res.s_pre>>>();
    k_scan_p2<<<1, SCAN_B, 0, g_res.s_pre>>>();
    k_scan_p3<<<SCAN_GRID, SCAN_B, 0, g_res.s_pre>>>();
    k_csr_fill<<<(NE + T - 1) / T, T, 0, g_res.s_pre>>>(src, dst);
    cudaEventRecord(g_res.e_csr, g_res.s_pre);

    // ---- main stream: dependency-free GEMMs run concurrently with prologue ----
    // layer-1 t (UNSCALED; outnorm applied per-edge in gather_h)
    k_gemm_mma<0, 0, 1><<<ggrid, T>>>(features, nullptr, W1, nullptr, pth, NN, DHID, DIN);
    // seq_fts = features @ fcW^T (independent)
    k_gemm_mma<1, 0, 0><<<ggrid, T>>>(features, nullptr, fcW, nullptr, seq_out, NN, DIN, DIN);

    // ---- join: CSR + norms required from here on ----
    cudaStreamWaitEvent(0, g_res.e_csr, 0);

    // layer 1 aggregate: h = relu(innorm * sum outnorm[s]*t[s] + b1)
    k_gather_h<<<gather_blocks, T>>>(pth, b1, h_out);

    // layer 2: t = (h @ [W2|W3]) * outnorm (fp16) ; z = gather+reparam
    k_gemm_mma<0, 1, 1><<<ggrid, T>>>(h_out, pon, W2, W3, pth, NN, DHID, DHID);
    k_gather_z<<<gather_blocks, T>>>(pth, b2, b3, noise, z_out);
}

// round 10
// speedup vs baseline: 1.1874x; 1.0505x over previous
#include <cuda_runtime.h>
#include <cuda_fp16.h>
#include <cstdint>
#include <cstddef>

#define NN   50000
#define NE   800000
#define DIN  256
#define DHID 256
#define DOUT 128

#define SCAN_B 256
#define SCAN_GRID ((NN + SCAN_B - 1) / SCAN_B)   // 196

// ---------------- scratch (device globals; no allocation allowed) ----------------
__device__ float g_outnorm[NN];
__device__ float g_innorm[NN];
__device__ int   g_outc[NN];
__device__ int   g_inc[NN];
__device__ int   g_rowptr[NN + 1];
__device__ int   g_cursor[NN];
__device__ int   g_poff[SCAN_B];                 // block partial sums -> offsets
__device__ int   g_csrc[NE];                     // src node per CSR slot (by dst)
__device__ __half g_th[(size_t)NN * DHID];       // pre-agg features (fp16, both layers)

// ---------------- degree / norm / CSR kernels ----------------
__global__ void k_zero_counts() {
    int i = blockIdx.x * blockDim.x + threadIdx.x;
    if (i < NN) { g_outc[i] = 0; g_inc[i] = 0; }
}

__global__ void k_degree(const int* __restrict__ src, const int* __restrict__ dst) {
    int e = blockIdx.x * blockDim.x + threadIdx.x;
    if (e < NE) {
        atomicAdd(&g_outc[src[e]], 1);
        atomicAdd(&g_inc[dst[e]], 1);
    }
}

__global__ void k_fin_norms() {
    int i = blockIdx.x * blockDim.x + threadIdx.x;
    if (i < NN) {
        g_outnorm[i] = rsqrtf(fmaxf((float)g_outc[i], 1.f));
        g_innorm[i]  = rsqrtf(fmaxf((float)g_inc[i], 1.f));
    }
}

// ---- 3-phase multi-block exclusive scan of g_inc -> g_rowptr / g_cursor ----
__global__ void k_scan_p1() {
    __shared__ int ws[8];
    int i = blockIdx.x * SCAN_B + threadIdx.x;
    int lane = threadIdx.x & 31, wid = threadIdx.x >> 5;
    int v = (i < NN) ? g_inc[i] : 0;
#pragma unroll
    for (int o = 16; o > 0; o >>= 1) v += __shfl_down_sync(0xffffffffu, v, o);
    if (lane == 0) ws[wid] = v;
    __syncthreads();
    if (wid == 0) {
        int s = (lane < 8) ? ws[lane] : 0;
#pragma unroll
        for (int o = 4; o > 0; o >>= 1) s += __shfl_down_sync(0xffffffffu, s, o);
        if (lane == 0) g_poff[blockIdx.x] = s;
    }
}

__global__ void k_scan_p2() {
    __shared__ int ws[8];
    int tid = threadIdx.x, lane = tid & 31, wid = tid >> 5;
    int v = (tid < SCAN_GRID) ? g_poff[tid] : 0;
    int x = v;
#pragma unroll
    for (int o = 1; o < 32; o <<= 1) {
        int y = __shfl_up_sync(0xffffffffu, x, o);
        if (lane >= o) x += y;
    }
    if (lane == 31) ws[wid] = x;
    __syncthreads();
    if (wid == 0 && lane < 8) {
        int s = ws[lane];
        int xs = s;
#pragma unroll
        for (int o = 1; o < 8; o <<= 1) {
            int y = __shfl_up_sync(0xffu, xs, o);
            if (lane >= o) xs += y;
        }
        ws[lane] = xs - s;
    }
    __syncthreads();
    g_poff[tid] = ws[wid] + x - v;
}

__global__ void k_scan_p3() {
    __shared__ int ws[8];
    int i = blockIdx.x * SCAN_B + threadIdx.x;
    int lane = threadIdx.x & 31, wid = threadIdx.x >> 5;
    int v = (i < NN) ? g_inc[i] : 0;
    int x = v;
#pragma unroll
    for (int o = 1; o < 32; o <<= 1) {
        int y = __shfl_up_sync(0xffffffffu, x, o);
        if (lane >= o) x += y;
    }
    if (lane == 31) ws[wid] = x;
    __syncthreads();
    if (wid == 0 && lane < 8) {
        int s = ws[lane];
        int xs = s;
#pragma unroll
        for (int o = 1; o < 8; o <<= 1) {
            int y = __shfl_up_sync(0xffu, xs, o);
            if (lane >= o) xs += y;
        }
        ws[lane] = xs - s;
    }
    __syncthreads();
    if (i < NN) {
        int excl = g_poff[blockIdx.x] + ws[wid] + x - v;
        g_rowptr[i] = excl;
        g_cursor[i] = excl;
    }
    if (blockIdx.x == 0 && threadIdx.x == 0) g_rowptr[NN] = NE;
}

__global__ void k_csr_fill(const int* __restrict__ src, const int* __restrict__ dst) {
    int e = blockIdx.x * blockDim.x + threadIdx.x;
    if (e < NE) {
        int pos = atomicAdd(&g_cursor[dst[e]], 1);
        g_csrc[pos] = src[e];
    }
}

// ---------------- fp16 gather SpMM + fused epilogues ----------------
// a[0..7] += s * (8 halfs of v)
__device__ __forceinline__ void acc8_f16(float* a, uint4 v, float s) {
    __half2 p0 = *(__half2*)&v.x;
    __half2 p1 = *(__half2*)&v.y;
    __half2 p2 = *(__half2*)&v.z;
    __half2 p3 = *(__half2*)&v.w;
    float2 f0 = __half22float2(p0);
    float2 f1 = __half22float2(p1);
    float2 f2 = __half22float2(p2);
    float2 f3 = __half22float2(p3);
    a[0] = fmaf(f0.x, s, a[0]); a[1] = fmaf(f0.y, s, a[1]);
    a[2] = fmaf(f1.x, s, a[2]); a[3] = fmaf(f1.y, s, a[3]);
    a[4] = fmaf(f2.x, s, a[4]); a[5] = fmaf(f2.y, s, a[5]);
    a[6] = fmaf(f3.x, s, a[6]); a[7] = fmaf(f3.y, s, a[7]);
}

// h = relu(in_norm * sum_{src in N(dst)} outnorm[src]*t[src] + b1)   (t fp16 UNSCALED)
__global__ void k_gather_h(const __half* __restrict__ t, const float* __restrict__ b1,
                           float* __restrict__ h) {
    int node = (blockIdx.x * blockDim.x + threadIdx.x) >> 5;
    int lane = threadIdx.x & 31;
    if (node >= NN) return;
    int beg = g_rowptr[node], end = g_rowptr[node + 1];
    float a[8];
#pragma unroll
    for (int i = 0; i < 8; i++) a[i] = 0.f;
    int j = beg;
    for (; j + 1 < end; j += 2) {
        int s0 = g_csrc[j], s1 = g_csrc[j + 1];
        float on0 = g_outnorm[s0], on1 = g_outnorm[s1];
        uint4 v0 = ((const uint4*)(t + (size_t)s0 * DHID))[lane];
        uint4 v1 = ((const uint4*)(t + (size_t)s1 * DHID))[lane];
        acc8_f16(a, v0, on0);
        acc8_f16(a, v1, on1);
    }
    if (j < end) {
        int s0 = g_csrc[j];
        float on0 = g_outnorm[s0];
        uint4 v = ((const uint4*)(t + (size_t)s0 * DHID))[lane];
        acc8_f16(a, v, on0);
    }
    float s = g_innorm[node];
    const float* bp = b1 + lane * 8;
    float4 bb0 = *(const float4*)bp;
    float4 bb1 = *(const float4*)(bp + 4);
    float4 o0, o1;
    o0.x = fmaxf(fmaf(a[0], s, bb0.x), 0.f); o0.y = fmaxf(fmaf(a[1], s, bb0.y), 0.f);
    o0.z = fmaxf(fmaf(a[2], s, bb0.z), 0.f); o0.w = fmaxf(fmaf(a[3], s, bb0.w), 0.f);
    o1.x = fmaxf(fmaf(a[4], s, bb1.x), 0.f); o1.y = fmaxf(fmaf(a[5], s, bb1.y), 0.f);
    o1.z = fmaxf(fmaf(a[6], s, bb1.z), 0.f); o1.w = fmaxf(fmaf(a[7], s, bb1.w), 0.f);
    float* hp = h + (size_t)node * DHID + lane * 8;
    *(float4*)hp = o0;
    *(float4*)(hp + 4) = o1;
}

// z = relu(mean*in + b2) + noise * exp(logstd*in + b3)   (t fp16, pre-scaled by outnorm)
// lanes 0-15 accumulate mean cols (8 each), lanes 16-31 logstd cols.
__global__ void k_gather_z(const __half* __restrict__ t,
                           const float* __restrict__ b2, const float* __restrict__ b3,
                           const float* __restrict__ noise, float* __restrict__ z) {
    int node = (blockIdx.x * blockDim.x + threadIdx.x) >> 5;
    int lane = threadIdx.x & 31;
    if (node >= NN) return;
    int beg = g_rowptr[node], end = g_rowptr[node + 1];
    float a[8];
#pragma unroll
    for (int i = 0; i < 8; i++) a[i] = 0.f;
    int j = beg;
    for (; j + 1 < end; j += 2) {
        int s0 = g_csrc[j], s1 = g_csrc[j + 1];
        uint4 v0 = ((const uint4*)(t + (size_t)s0 * DHID))[lane];
        uint4 v1 = ((const uint4*)(t + (size_t)s1 * DHID))[lane];
        acc8_f16(a, v0, 1.f);
        acc8_f16(a, v1, 1.f);
    }
    if (j < end) {
        uint4 v = ((const uint4*)(t + (size_t)g_csrc[j] * DHID))[lane];
        acc8_f16(a, v, 1.f);
    }
    // bring logstd accumulators (lanes 16-31) down to lanes 0-15
    float l[8];
#pragma unroll
    for (int i = 0; i < 8; i++) l[i] = __shfl_down_sync(0xffffffffu, a[i], 16);
    if (lane < 16) {
        float s = g_innorm[node];
        const float* bmp = b2 + lane * 8;
        const float* blp = b3 + lane * 8;
        const float* nvp = noise + (size_t)node * DOUT + lane * 8;
        float4 bm0 = *(const float4*)bmp,        bm1 = *(const float4*)(bmp + 4);
        float4 bl0 = *(const float4*)blp,        bl1 = *(const float4*)(blp + 4);
        float4 n0  = *(const float4*)nvp,        n1  = *(const float4*)(nvp + 4);
        float4 r0, r1;
        r0.x = fmaxf(fmaf(a[0], s, bm0.x), 0.f) + n0.x * expf(fmaf(l[0], s, bl0.x));
        r0.y = fmaxf(fmaf(a[1], s, bm0.y), 0.f) + n0.y * expf(fmaf(l[1], s, bl0.y));
        r0.z = fmaxf(fmaf(a[2], s, bm0.z), 0.f) + n0.z * expf(fmaf(l[2], s, bl0.z));
        r0.w = fmaxf(fmaf(a[3], s, bm0.w), 0.f) + n0.w * expf(fmaf(l[3], s, bl0.w));
        r1.x = fmaxf(fmaf(a[4], s, bm1.x), 0.f) + n1.x * expf(fmaf(l[4], s, bl1.x));
        r1.y = fmaxf(fmaf(a[5], s, bm1.y), 0.f) + n1.y * expf(fmaf(l[5], s, bl1.y));
        r1.z = fmaxf(fmaf(a[6], s, bm1.z), 0.f) + n1.z * expf(fmaf(l[6], s, bl1.z));
        r1.w = fmaxf(fmaf(a[7], s, bm1.w), 0.f) + n1.w * expf(fmaf(l[7], s, bl1.w));
        float* zp = z + (size_t)node * DOUT + lane * 8;
        *(float4*)zp = r0;
        *(float4*)(zp + 4) = r1;
    }
}

// ---------------- tf32 / cp.async helpers ----------------
__device__ __forceinline__ uint32_t f2tf32(float x) {
    uint32_t r;
    asm("cvt.rna.tf32.f32 %0, %1;" : "=r"(r) : "f"(x));
    return r;
}

__device__ __forceinline__ void mma_tf32(float* c, const uint32_t* a, const uint32_t* b) {
    asm volatile(
        "mma.sync.aligned.m16n8k8.row.col.f32.tf32.tf32.f32 "
        "{%0,%1,%2,%3}, {%4,%5,%6,%7}, {%8,%9}, {%0,%1,%2,%3};"
        : "+f"(c[0]), "+f"(c[1]), "+f"(c[2]), "+f"(c[3])
        : "r"(a[0]), "r"(a[1]), "r"(a[2]), "r"(a[3]), "r"(b[0]), "r"(b[1]));
}

__device__ __forceinline__ void cp16(uint32_t dst, const void* src) {
    asm volatile("cp.async.cg.shared.global [%0], [%1], 16;" :: "r"(dst), "l"(src));
}
__device__ __forceinline__ void cp_commit() { asm volatile("cp.async.commit_group;"); }
template<int N>
__device__ __forceinline__ void cp_wait() { asm volatile("cp.async.wait_group %0;" :: "n"(N)); }

// ---------------- tensor-core GEMM (cp.async double-buffered) ----------------
// C[M,Ncols] = (A @ B) * rowscale (applied to output rows)
// TRANSB=0: B(k,n)=B[k*ld+n]; SPLITB: cols [0,128)->B0, [128,256)->B1 (ld=DOUT)
// TRANSB=1: B(k,n)=B0[n*K+k]
// OUTHALF=1: C is __half* (packed half2 stores); else float*.
template<int TRANSB, int SPLITB, int OUTHALF>
__global__ void __launch_bounds__(256, 2)
k_gemm_mma(const float* __restrict__ A, const float* __restrict__ rowscale,
           const float* __restrict__ B0, const float* __restrict__ B1,
           void* __restrict__ Cv, int M, int Ncols, int K)
{
    constexpr int BM = 128, BN = 128, BK = 16;
    constexpr int ALD = BK + 4;
    constexpr int BSZ = TRANSB ? (BN * ALD) : (BK * (BN + 8));
    __shared__ float As[2][BM * ALD];
    __shared__ float Bs[2][BSZ];

    const int tid  = threadIdx.x;
    const int lane = tid & 31;
    const int warp = tid >> 5;
    const int row0 = blockIdx.y * BM;
    const int col0 = blockIdx.x * BN;
    const int warpM = (warp >> 2) * 64;
    const int warpN = (warp & 3) * 32;

    float acc[4][4][4];
#pragma unroll
    for (int i = 0; i < 4; i++)
#pragma unroll
        for (int j = 0; j < 4; j++)
#pragma unroll
            for (int r = 0; r < 4; r++) acc[i][j][r] = 0.f;

    const int ar = tid >> 2;
    const int ak4 = tid & 3;
    const int bkr = tid >> 5;
    const int bn4 = tid & 31;

    const float* bbase;
    int bld = 0;
    if constexpr (TRANSB) {
        bbase = B0;
    } else if constexpr (SPLITB) {
        bbase = (col0 == 0) ? B0 : B1;
        bld = DOUT;
    } else {
        bbase = B0 + col0;
        bld = Ncols;
    }

    auto stage = [&](int k0, int buf) {
#pragma unroll
        for (int i = 0; i < 2; i++) {
            int r = ar + i * 64;
            int gr = row0 + r;
            if (gr >= M) gr = M - 1;
            cp16((uint32_t)__cvta_generic_to_shared(&As[buf][r * ALD + ak4 * 4]),
                 A + (size_t)gr * K + k0 + ak4 * 4);
        }
        if constexpr (TRANSB) {
#pragma unroll
            for (int i = 0; i < 2; i++) {
                int r = ar + i * 64;
                cp16((uint32_t)__cvta_generic_to_shared(&Bs[buf][r * ALD + ak4 * 4]),
                     bbase + (size_t)(col0 + r) * K + k0 + ak4 * 4);
            }
        } else {
#pragma unroll
            for (int i = 0; i < 2; i++) {
                int k = bkr + i * 8;
                cp16((uint32_t)__cvta_generic_to_shared(&Bs[buf][k * (BN + 8) + bn4 * 4]),
                     bbase + (size_t)(k0 + k) * bld + bn4 * 4);
            }
        }
    };

    const int NT = K / BK;
    stage(0, 0);
    cp_commit();

    for (int t = 0; t < NT; t++) {
        int buf = t & 1;
        if (t + 1 < NT) {
            stage((t + 1) * BK, buf ^ 1);
            cp_commit();
            cp_wait<1>();
        } else {
            cp_wait<0>();
        }
        __syncthreads();

#pragma unroll
        for (int ks = 0; ks < 2; ks++) {
            uint32_t a[4][4], b[4][2];
#pragma unroll
            for (int mi = 0; mi < 4; mi++) {
                const float* ap = &As[buf][(warpM + mi * 16 + (lane >> 2)) * ALD + ks * 8 + (lane & 3)];
                a[mi][0] = f2tf32(ap[0]);
                a[mi][1] = f2tf32(ap[8 * ALD]);
                a[mi][2] = f2tf32(ap[4]);
                a[mi][3] = f2tf32(ap[8 * ALD + 4]);
            }
#pragma unroll
            for (int ni = 0; ni < 4; ni++) {
                if constexpr (TRANSB) {
                    const float* bp = &Bs[buf][(warpN + ni * 8 + (lane >> 2)) * ALD + ks * 8 + (lane & 3)];
                    b[ni][0] = f2tf32(bp[0]);
                    b[ni][1] = f2tf32(bp[4]);
                } else {
                    const float* bp = &Bs[buf][(ks * 8 + (lane & 3)) * (BN + 8) + warpN + ni * 8 + (lane >> 2)];
                    b[ni][0] = f2tf32(bp[0]);
                    b[ni][1] = f2tf32(bp[4 * (BN + 8)]);
                }
            }
#pragma unroll
            for (int mi = 0; mi < 4; mi++)
#pragma unroll
                for (int ni = 0; ni < 4; ni++)
                    mma_tf32(acc[mi][ni], a[mi], b[ni]);
        }
        __syncthreads();
    }

    // epilogue: rowscale + store (fp32 or packed half2)
#pragma unroll
    for (int mi = 0; mi < 4; mi++) {
        int gr0 = row0 + warpM + mi * 16 + (lane >> 2);
        float s0 = 1.f, s1 = 1.f;
        if (rowscale) {
            if (gr0 < M)     s0 = rowscale[gr0];
            if (gr0 + 8 < M) s1 = rowscale[gr0 + 8];
        }
#pragma unroll
        for (int ni = 0; ni < 4; ni++) {
            int col = col0 + warpN + ni * 8 + (lane & 3) * 2;
            if constexpr (OUTHALF) {
                __half* Ch = (__half*)Cv;
                if (gr0 < M)
                    *(__half2*)(Ch + (size_t)gr0 * Ncols + col) =
                        __float22half2_rn(make_float2(acc[mi][ni][0] * s0, acc[mi][ni][1] * s0));
                if (gr0 + 8 < M)
                    *(__half2*)(Ch + (size_t)(gr0 + 8) * Ncols + col) =
                        __float22half2_rn(make_float2(acc[mi][ni][2] * s1, acc[mi][ni][3] * s1));
            } else {
                float* C = (float*)Cv;
                if (gr0 < M)
                    *(float2*)(C + (size_t)gr0 * Ncols + col) =
                        make_float2(acc[mi][ni][0] * s0, acc[mi][ni][1] * s0);
                if (gr0 + 8 < M)
                    *(float2*)(C + (size_t)(gr0 + 8) * Ncols + col) =
                        make_float2(acc[mi][ni][2] * s1, acc[mi][ni][3] * s1);
            }
        }
    }
}

// ---------------- stream/event singletons (host resources, created once) ----------
namespace {
struct HxRes {
    cudaStream_t s_pre = nullptr, s_g3 = nullptr;
    cudaEvent_t  e_fork = nullptr, e_csr = nullptr, e_g1 = nullptr, e_g3 = nullptr;
    HxRes() {
        cudaStreamCreateWithFlags(&s_pre, cudaStreamNonBlocking);
        cudaStreamCreateWithFlags(&s_g3,  cudaStreamNonBlocking);
        cudaEventCreateWithFlags(&e_fork, cudaEventDisableTiming);
        cudaEventCreateWithFlags(&e_csr,  cudaEventDisableTiming);
        cudaEventCreateWithFlags(&e_g1,   cudaEventDisableTiming);
        cudaEventCreateWithFlags(&e_g3,   cudaEventDisableTiming);
    }
};
HxRes g_res;
}

// ---------------- launch ----------------
extern "C" void kernel_launch(void* const* d_in, const int* in_sizes, int n_in,
                              void* d_out, int out_size)
{
    const float* features = (const float*)d_in[0];
    const float* noise    = (const float*)d_in[1];
    const float* W1       = (const float*)d_in[2];
    const float* b1       = (const float*)d_in[3];
    const float* W2       = (const float*)d_in[4];
    const float* b2       = (const float*)d_in[5];
    const float* W3       = (const float*)d_in[6];
    const float* b3       = (const float*)d_in[7];
    const float* fcW      = (const float*)d_in[8];
    const int*   src      = (const int*)d_in[9];
    const int*   dst      = (const int*)d_in[10];

    float* out     = (float*)d_out;
    float* z_out   = out;                                 // [NN, 128]
    float* h_out   = out + (size_t)NN * DOUT;             // [NN, 256]
    float* seq_out = h_out + (size_t)NN * DHID;           // [NN, 256]

    __half* pth;
    float*  pon;
    cudaGetSymbolAddress((void**)&pth, g_th);
    cudaGetSymbolAddress((void**)&pon, g_outnorm);

    const int T = 256;
    dim3 ggrid(2, (NN + 127) / 128);
    const int gather_blocks = (NN * 32 + T - 1) / T;

    // ---- fork: CSR prologue on side stream (concurrent with gemm1) ----
    cudaEventRecord(g_res.e_fork, 0);
    cudaStreamWaitEvent(g_res.s_pre, g_res.e_fork, 0);
    k_zero_counts<<<(NN + T - 1) / T, T, 0, g_res.s_pre>>>();
    k_degree<<<(NE + T - 1) / T, T, 0, g_res.s_pre>>>(src, dst);
    k_fin_norms<<<(NN + T - 1) / T, T, 0, g_res.s_pre>>>();
    k_scan_p1<<<SCAN_GRID, SCAN_B, 0, g_res.s_pre>>>();
    k_scan_p2<<<1, SCAN_B, 0, g_res.s_pre>>>();
    k_scan_p3<<<SCAN_GRID, SCAN_B, 0, g_res.s_pre>>>();
    k_csr_fill<<<(NE + T - 1) / T, T, 0, g_res.s_pre>>>(src, dst);
    cudaEventRecord(g_res.e_csr, g_res.s_pre);

    // ---- main: gemm1 (critical path head) ----
    k_gemm_mma<0, 0, 1><<<ggrid, T>>>(features, nullptr, W1, nullptr, pth, NN, DHID, DIN);
    cudaEventRecord(g_res.e_g1, 0);

    // ---- side: gemm3 (seq_fts) after gemm1, overlapping gather_h/gemm2/gather_z ----
    cudaStreamWaitEvent(g_res.s_g3, g_res.e_g1, 0);
    k_gemm_mma<1, 0, 0><<<ggrid, T, 0, g_res.s_g3>>>(features, nullptr, fcW, nullptr,
                                                     seq_out, NN, DIN, DIN);
    cudaEventRecord(g_res.e_g3, g_res.s_g3);

    // ---- main: join CSR, then layer-1 aggregate + layer 2 ----
    cudaStreamWaitEvent(0, g_res.e_csr, 0);
    k_gather_h<<<gather_blocks, T>>>(pth, b1, h_out);

    k_gemm_mma<0, 1, 1><<<ggrid, T>>>(h_out, pon, W2, W3, pth, NN, DHID, DHID);
    k_gather_z<<<gather_blocks, T>>>(pth, b2, b3, noise, z_out);

    // ---- final join: seq_fts must be complete before graph end ----
    cudaStreamWaitEvent(0, g_res.e_g3, 0);
}

// round 11
// speedup vs baseline: 1.3352x; 1.1245x over previous
#include <cuda_runtime.h>
#include <cuda_fp16.h>
#include <cstdint>
#include <cstddef>

#define NN   50000
#define NE   800000
#define DIN  256
#define DHID 256
#define DOUT 128

#define SCAN_B 256
#define SCAN_GRID ((NN + SCAN_B - 1) / SCAN_B)   // 196

// ---------------- scratch (device globals; no allocation allowed) ----------------
__device__ float g_outnorm[NN];
__device__ float g_innorm[NN];
__device__ int   g_outc[NN];
__device__ int   g_inc[NN];
__device__ int   g_rowptr[NN + 1];
__device__ int   g_cursor[NN];
__device__ int   g_poff[SCAN_B];                 // block partial sums -> offsets
__device__ int   g_csrc[NE];                     // src node per CSR slot (by dst)
__device__ __half g_th[(size_t)NN * DHID];       // pre-agg features t (fp16)
__device__ __half g_hh[(size_t)NN * DHID];       // fp16 copy of h (gemm2 input)
__device__ __half g_fh[(size_t)NN * DIN];        // fp16 features
__device__ __half g_w1h[DIN * DHID];             // W1^T  [n][k] fp16
__device__ __half g_w23h[DHID * DHID];           // [W2|W3]^T [n][k] fp16
__device__ __half g_fcwh[DHID * DIN];            // fcW (already [n][k]) fp16

// ---------------- conversion kernels ----------------
__global__ void k_conv_feat(const float* __restrict__ f) {
    int i = blockIdx.x * blockDim.x + threadIdx.x;
    if (i >= NN * (DIN / 4)) return;
    float4 v = ((const float4*)f)[i];
    __half2 h0 = __float22half2_rn(make_float2(v.x, v.y));
    __half2 h1 = __float22half2_rn(make_float2(v.z, v.w));
    uint2 o;
    o.x = *(uint32_t*)&h0;
    o.y = *(uint32_t*)&h1;
    ((uint2*)g_fh)[i] = o;
}

// out[n*256+k] = S[k*256+n]   (W1 -> g_w1h)
__global__ void k_conv_w1(const float* __restrict__ S) {
    int t = blockIdx.x * blockDim.x + threadIdx.x;   // 65536
    int n = t >> 8, k = t & 255;
    g_w1h[t] = __float2half(S[k * 256 + n]);
}

// g_w23h[(n0+n)*256+k] = S[k*128+n], n in [0,128)
__global__ void k_conv_w128(const float* __restrict__ S, int n0) {
    int t = blockIdx.x * blockDim.x + threadIdx.x;   // 32768
    int n = t >> 8, k = t & 255;
    g_w23h[(size_t)(n0 + n) * 256 + k] = __float2half(S[k * 128 + n]);
}

// fcW is [HID][IN] = [n][k] already; elementwise convert
__global__ void k_conv_fcw(const float* __restrict__ S) {
    int t = blockIdx.x * blockDim.x + threadIdx.x;   // 65536
    g_fcwh[t] = __float2half(S[t]);
}

// ---------------- degree / norm / CSR kernels ----------------
__global__ void k_zero_counts() {
    int i = blockIdx.x * blockDim.x + threadIdx.x;
    if (i < NN) { g_outc[i] = 0; g_inc[i] = 0; }
}

__global__ void k_degree(const int* __restrict__ src, const int* __restrict__ dst) {
    int e = blockIdx.x * blockDim.x + threadIdx.x;
    if (e < NE) {
        atomicAdd(&g_outc[src[e]], 1);
        atomicAdd(&g_inc[dst[e]], 1);
    }
}

__global__ void k_fin_norms() {
    int i = blockIdx.x * blockDim.x + threadIdx.x;
    if (i < NN) {
        g_outnorm[i] = rsqrtf(fmaxf((float)g_outc[i], 1.f));
        g_innorm[i]  = rsqrtf(fmaxf((float)g_inc[i], 1.f));
    }
}

// ---- 3-phase multi-block exclusive scan of g_inc -> g_rowptr / g_cursor ----
__global__ void k_scan_p1() {
    __shared__ int ws[8];
    int i = blockIdx.x * SCAN_B + threadIdx.x;
    int lane = threadIdx.x & 31, wid = threadIdx.x >> 5;
    int v = (i < NN) ? g_inc[i] : 0;
#pragma unroll
    for (int o = 16; o > 0; o >>= 1) v += __shfl_down_sync(0xffffffffu, v, o);
    if (lane == 0) ws[wid] = v;
    __syncthreads();
    if (wid == 0) {
        int s = (lane < 8) ? ws[lane] : 0;
#pragma unroll
        for (int o = 4; o > 0; o >>= 1) s += __shfl_down_sync(0xffffffffu, s, o);
        if (lane == 0) g_poff[blockIdx.x] = s;
    }
}

__global__ void k_scan_p2() {
    __shared__ int ws[8];
    int tid = threadIdx.x, lane = tid & 31, wid = tid >> 5;
    int v = (tid < SCAN_GRID) ? g_poff[tid] : 0;
    int x = v;
#pragma unroll
    for (int o = 1; o < 32; o <<= 1) {
        int y = __shfl_up_sync(0xffffffffu, x, o);
        if (lane >= o) x += y;
    }
    if (lane == 31) ws[wid] = x;
    __syncthreads();
    if (wid == 0 && lane < 8) {
        int s = ws[lane];
        int xs = s;
#pragma unroll
        for (int o = 1; o < 8; o <<= 1) {
            int y = __shfl_up_sync(0xffu, xs, o);
            if (lane >= o) xs += y;
        }
        ws[lane] = xs - s;
    }
    __syncthreads();
    g_poff[tid] = ws[wid] + x - v;
}

__global__ void k_scan_p3() {
    __shared__ int ws[8];
    int i = blockIdx.x * SCAN_B + threadIdx.x;
    int lane = threadIdx.x & 31, wid = threadIdx.x >> 5;
    int v = (i < NN) ? g_inc[i] : 0;
    int x = v;
#pragma unroll
    for (int o = 1; o < 32; o <<= 1) {
        int y = __shfl_up_sync(0xffffffffu, x, o);
        if (lane >= o) x += y;
    }
    if (lane == 31) ws[wid] = x;
    __syncthreads();
    if (wid == 0 && lane < 8) {
        int s = ws[lane];
        int xs = s;
#pragma unroll
        for (int o = 1; o < 8; o <<= 1) {
            int y = __shfl_up_sync(0xffu, xs, o);
            if (lane >= o) xs += y;
        }
        ws[lane] = xs - s;
    }
    __syncthreads();
    if (i < NN) {
        int excl = g_poff[blockIdx.x] + ws[wid] + x - v;
        g_rowptr[i] = excl;
        g_cursor[i] = excl;
    }
    if (blockIdx.x == 0 && threadIdx.x == 0) g_rowptr[NN] = NE;
}

__global__ void k_csr_fill(const int* __restrict__ src, const int* __restrict__ dst) {
    int e = blockIdx.x * blockDim.x + threadIdx.x;
    if (e < NE) {
        int pos = atomicAdd(&g_cursor[dst[e]], 1);
        g_csrc[pos] = src[e];
    }
}

// ---------------- fp16 gather SpMM + fused epilogues ----------------
// a[0..7] += s * (8 halfs of v)
__device__ __forceinline__ void acc8_f16(float* a, uint4 v, float s) {
    __half2 p0 = *(__half2*)&v.x;
    __half2 p1 = *(__half2*)&v.y;
    __half2 p2 = *(__half2*)&v.z;
    __half2 p3 = *(__half2*)&v.w;
    float2 f0 = __half22float2(p0);
    float2 f1 = __half22float2(p1);
    float2 f2 = __half22float2(p2);
    float2 f3 = __half22float2(p3);
    a[0] = fmaf(f0.x, s, a[0]); a[1] = fmaf(f0.y, s, a[1]);
    a[2] = fmaf(f1.x, s, a[2]); a[3] = fmaf(f1.y, s, a[3]);
    a[4] = fmaf(f2.x, s, a[4]); a[5] = fmaf(f2.y, s, a[5]);
    a[6] = fmaf(f3.x, s, a[6]); a[7] = fmaf(f3.y, s, a[7]);
}

// h = relu(in_norm * sum outnorm[src]*t[src] + b1); writes fp32 h + fp16 copy
__global__ void k_gather_h(const __half* __restrict__ t, const float* __restrict__ b1,
                           float* __restrict__ h, __half* __restrict__ hh) {
    int node = (blockIdx.x * blockDim.x + threadIdx.x) >> 5;
    int lane = threadIdx.x & 31;
    if (node >= NN) return;
    int beg = g_rowptr[node], end = g_rowptr[node + 1];
    float a[8];
#pragma unroll
    for (int i = 0; i < 8; i++) a[i] = 0.f;
    int j = beg;
    for (; j + 1 < end; j += 2) {
        int s0 = g_csrc[j], s1 = g_csrc[j + 1];
        float on0 = g_outnorm[s0], on1 = g_outnorm[s1];
        uint4 v0 = ((const uint4*)(t + (size_t)s0 * DHID))[lane];
        uint4 v1 = ((const uint4*)(t + (size_t)s1 * DHID))[lane];
        acc8_f16(a, v0, on0);
        acc8_f16(a, v1, on1);
    }
    if (j < end) {
        int s0 = g_csrc[j];
        float on0 = g_outnorm[s0];
        uint4 v = ((const uint4*)(t + (size_t)s0 * DHID))[lane];
        acc8_f16(a, v, on0);
    }
    float s = g_innorm[node];
    const float* bp = b1 + lane * 8;
    float4 bb0 = *(const float4*)bp;
    float4 bb1 = *(const float4*)(bp + 4);
    float4 o0, o1;
    o0.x = fmaxf(fmaf(a[0], s, bb0.x), 0.f); o0.y = fmaxf(fmaf(a[1], s, bb0.y), 0.f);
    o0.z = fmaxf(fmaf(a[2], s, bb0.z), 0.f); o0.w = fmaxf(fmaf(a[3], s, bb0.w), 0.f);
    o1.x = fmaxf(fmaf(a[4], s, bb1.x), 0.f); o1.y = fmaxf(fmaf(a[5], s, bb1.y), 0.f);
    o1.z = fmaxf(fmaf(a[6], s, bb1.z), 0.f); o1.w = fmaxf(fmaf(a[7], s, bb1.w), 0.f);
    float* hp = h + (size_t)node * DHID + lane * 8;
    *(float4*)hp = o0;
    *(float4*)(hp + 4) = o1;
    // fp16 copy for the layer-2 GEMM
    __half2 q0 = __float22half2_rn(make_float2(o0.x, o0.y));
    __half2 q1 = __float22half2_rn(make_float2(o0.z, o0.w));
    __half2 q2 = __float22half2_rn(make_float2(o1.x, o1.y));
    __half2 q3 = __float22half2_rn(make_float2(o1.z, o1.w));
    uint4 q;
    q.x = *(uint32_t*)&q0; q.y = *(uint32_t*)&q1;
    q.z = *(uint32_t*)&q2; q.w = *(uint32_t*)&q3;
    ((uint4*)(hh + (size_t)node * DHID))[lane] = q;
}

// z = relu(mean*in + b2) + noise * exp(logstd*in + b3)   (t fp16, pre-scaled by outnorm)
__global__ void k_gather_z(const __half* __restrict__ t,
                           const float* __restrict__ b2, const float* __restrict__ b3,
                           const float* __restrict__ noise, float* __restrict__ z) {
    int node = (blockIdx.x * blockDim.x + threadIdx.x) >> 5;
    int lane = threadIdx.x & 31;
    if (node >= NN) return;
    int beg = g_rowptr[node], end = g_rowptr[node + 1];
    float a[8];
#pragma unroll
    for (int i = 0; i < 8; i++) a[i] = 0.f;
    int j = beg;
    for (; j + 1 < end; j += 2) {
        int s0 = g_csrc[j], s1 = g_csrc[j + 1];
        uint4 v0 = ((const uint4*)(t + (size_t)s0 * DHID))[lane];
        uint4 v1 = ((const uint4*)(t + (size_t)s1 * DHID))[lane];
        acc8_f16(a, v0, 1.f);
        acc8_f16(a, v1, 1.f);
    }
    if (j < end) {
        uint4 v = ((const uint4*)(t + (size_t)g_csrc[j] * DHID))[lane];
        acc8_f16(a, v, 1.f);
    }
    float l[8];
#pragma unroll
    for (int i = 0; i < 8; i++) l[i] = __shfl_down_sync(0xffffffffu, a[i], 16);
    if (lane < 16) {
        float s = g_innorm[node];
        const float* bmp = b2 + lane * 8;
        const float* blp = b3 + lane * 8;
        const float* nvp = noise + (size_t)node * DOUT + lane * 8;
        float4 bm0 = *(const float4*)bmp,        bm1 = *(const float4*)(bmp + 4);
        float4 bl0 = *(const float4*)blp,        bl1 = *(const float4*)(blp + 4);
        float4 n0  = *(const float4*)nvp,        n1  = *(const float4*)(nvp + 4);
        float4 r0, r1;
        r0.x = fmaxf(fmaf(a[0], s, bm0.x), 0.f) + n0.x * expf(fmaf(l[0], s, bl0.x));
        r0.y = fmaxf(fmaf(a[1], s, bm0.y), 0.f) + n0.y * expf(fmaf(l[1], s, bl0.y));
        r0.z = fmaxf(fmaf(a[2], s, bm0.z), 0.f) + n0.z * expf(fmaf(l[2], s, bl0.z));
        r0.w = fmaxf(fmaf(a[3], s, bm0.w), 0.f) + n0.w * expf(fmaf(l[3], s, bl0.w));
        r1.x = fmaxf(fmaf(a[4], s, bm1.x), 0.f) + n1.x * expf(fmaf(l[4], s, bl1.x));
        r1.y = fmaxf(fmaf(a[5], s, bm1.y), 0.f) + n1.y * expf(fmaf(l[5], s, bl1.y));
        r1.z = fmaxf(fmaf(a[6], s, bm1.z), 0.f) + n1.z * expf(fmaf(l[6], s, bl1.z));
        r1.w = fmaxf(fmaf(a[7], s, bm1.w), 0.f) + n1.w * expf(fmaf(l[7], s, bl1.w));
        float* zp = z + (size_t)node * DOUT + lane * 8;
        *(float4*)zp = r0;
        *(float4*)(zp + 4) = r1;
    }
}

// ---------------- fp16 mma / cp.async helpers ----------------
__device__ __forceinline__ void mma_f16(float* c, const uint32_t* a, const uint32_t* b) {
    asm volatile(
        "mma.sync.aligned.m16n8k16.row.col.f32.f16.f16.f32 "
        "{%0,%1,%2,%3}, {%4,%5,%6,%7}, {%8,%9}, {%0,%1,%2,%3};"
        : "+f"(c[0]), "+f"(c[1]), "+f"(c[2]), "+f"(c[3])
        : "r"(a[0]), "r"(a[1]), "r"(a[2]), "r"(a[3]), "r"(b[0]), "r"(b[1]));
}

__device__ __forceinline__ void cp16(uint32_t dst, const void* src) {
    asm volatile("cp.async.cg.shared.global [%0], [%1], 16;" :: "r"(dst), "l"(src));
}
__device__ __forceinline__ void cp_commit() { asm volatile("cp.async.commit_group;"); }
template<int N>
__device__ __forceinline__ void cp_wait() { asm volatile("cp.async.wait_group %0;" :: "n"(N)); }

// ---------------- fp16 tensor-core GEMM ----------------
// C[M][256] = A[M][256](fp16, K-contig) @ B[256][256](fp16, [n][k]) ; * rowscale on rows
// OUTHALF: 1 -> __half* C ; 0 -> float* C
template<int OUTHALF>
__global__ void __launch_bounds__(256, 2)
k_gemm_f16(const __half* __restrict__ A, const float* __restrict__ rowscale,
           const __half* __restrict__ B, void* __restrict__ Cv, int M)
{
    constexpr int K = 256, NCOLS = 256;
    constexpr int BM = 128, BN = 128, BK = 32;
    constexpr int ALD = 40;                       // halfs per smem row (80B, 16B-mult)
    __shared__ __align__(16) __half As[2][BM * ALD];
    __shared__ __align__(16) __half Bs[2][BN * ALD];

    const int tid  = threadIdx.x;
    const int lane = tid & 31;
    const int warp = tid >> 5;
    const int row0 = blockIdx.y * BM;
    const int col0 = blockIdx.x * BN;
    const int warpM = (warp >> 2) * 64;
    const int warpN = (warp & 3) * 32;

    float acc[4][4][4];
#pragma unroll
    for (int i = 0; i < 4; i++)
#pragma unroll
        for (int j = 0; j < 4; j++)
#pragma unroll
            for (int r = 0; r < 4; r++) acc[i][j][r] = 0.f;

    auto stage = [&](int k0, int buf) {
#pragma unroll
        for (int i = 0; i < 2; i++) {
            int c = tid * 2 + i;                  // 512 chunks of 16B
            int r = c >> 2;
            int off = (c & 3) * 8;                // halfs
            int gr = row0 + r;
            if (gr >= M) gr = M - 1;
            cp16((uint32_t)__cvta_generic_to_shared(&As[buf][r * ALD + off]),
                 A + (size_t)gr * K + k0 + off);
            cp16((uint32_t)__cvta_generic_to_shared(&Bs[buf][r * ALD + off]),
                 B + (size_t)(col0 + r) * K + k0 + off);
        }
    };

    const int NT = K / BK;                        // 8
    stage(0, 0);
    cp_commit();

    for (int t = 0; t < NT; t++) {
        int buf = t & 1;
        if (t + 1 < NT) {
            stage((t + 1) * BK, buf ^ 1);
            cp_commit();
            cp_wait<1>();
        } else {
            cp_wait<0>();
        }
        __syncthreads();

#pragma unroll
        for (int ks = 0; ks < 2; ks++) {
            const int kb = ks * 16 + (lane & 3) * 2;
            uint32_t a[4][4], b[4][2];
#pragma unroll
            for (int mi = 0; mi < 4; mi++) {
                const __half* ap = &As[buf][(warpM + mi * 16 + (lane >> 2)) * ALD + kb];
                a[mi][0] = *(const uint32_t*)ap;
                a[mi][1] = *(const uint32_t*)(ap + 8 * ALD);
                a[mi][2] = *(const uint32_t*)(ap + 8);
                a[mi][3] = *(const uint32_t*)(ap + 8 * ALD + 8);
            }
#pragma unroll
            for (int ni = 0; ni < 4; ni++) {
                const __half* bp = &Bs[buf][(warpN + ni * 8 + (lane >> 2)) * ALD + kb];
                b[ni][0] = *(const uint32_t*)bp;
                b[ni][1] = *(const uint32_t*)(bp + 8);
            }
#pragma unroll
            for (int mi = 0; mi < 4; mi++)
#pragma unroll
                for (int ni = 0; ni < 4; ni++)
                    mma_f16(acc[mi][ni], a[mi], b[ni]);
        }
        __syncthreads();
    }

    // epilogue: rowscale + store
#pragma unroll
    for (int mi = 0; mi < 4; mi++) {
        int gr0 = row0 + warpM + mi * 16 + (lane >> 2);
        float s0 = 1.f, s1 = 1.f;
        if (rowscale) {
            if (gr0 < M)     s0 = rowscale[gr0];
            if (gr0 + 8 < M) s1 = rowscale[gr0 + 8];
        }
#pragma unroll
        for (int ni = 0; ni < 4; ni++) {
            int col = col0 + warpN + ni * 8 + (lane & 3) * 2;
            if constexpr (OUTHALF) {
                __half* Ch = (__half*)Cv;
                if (gr0 < M)
                    *(__half2*)(Ch + (size_t)gr0 * NCOLS + col) =
                        __float22half2_rn(make_float2(acc[mi][ni][0] * s0, acc[mi][ni][1] * s0));
                if (gr0 + 8 < M)
                    *(__half2*)(Ch + (size_t)(gr0 + 8) * NCOLS + col) =
                        __float22half2_rn(make_float2(acc[mi][ni][2] * s1, acc[mi][ni][3] * s1));
            } else {
                float* C = (float*)Cv;
                if (gr0 < M)
                    *(float2*)(C + (size_t)gr0 * NCOLS + col) =
                        make_float2(acc[mi][ni][0] * s0, acc[mi][ni][1] * s0);
                if (gr0 + 8 < M)
                    *(float2*)(C + (size_t)(gr0 + 8) * NCOLS + col) =
                        make_float2(acc[mi][ni][2] * s1, acc[mi][ni][3] * s1);
            }
        }
    }
}

// ---------------- stream/event singletons (host resources, created once) ----------
namespace {
struct HxRes {
    cudaStream_t s_pre = nullptr, s_g3 = nullptr;
    cudaEvent_t  e_fork = nullptr, e_w = nullptr, e_csr = nullptr,
                 e_g1 = nullptr, e_g3 = nullptr;
    HxRes() {
        cudaStreamCreateWithFlags(&s_pre, cudaStreamNonBlocking);
        cudaStreamCreateWithFlags(&s_g3,  cudaStreamNonBlocking);
        cudaEventCreateWithFlags(&e_fork, cudaEventDisableTiming);
        cudaEventCreateWithFlags(&e_w,    cudaEventDisableTiming);
        cudaEventCreateWithFlags(&e_csr,  cudaEventDisableTiming);
        cudaEventCreateWithFlags(&e_g1,   cudaEventDisableTiming);
        cudaEventCreateWithFlags(&e_g3,   cudaEventDisableTiming);
    }
};
HxRes g_res;
}

// ---------------- launch ----------------
extern "C" void kernel_launch(void* const* d_in, const int* in_sizes, int n_in,
                              void* d_out, int out_size)
{
    const float* features = (const float*)d_in[0];
    const float* noise    = (const float*)d_in[1];
    const float* W1       = (const float*)d_in[2];
    const float* b1       = (const float*)d_in[3];
    const float* W2       = (const float*)d_in[4];
    const float* b2       = (const float*)d_in[5];
    const float* W3       = (const float*)d_in[6];
    const float* b3       = (const float*)d_in[7];
    const float* fcW      = (const float*)d_in[8];
    const int*   src      = (const int*)d_in[9];
    const int*   dst      = (const int*)d_in[10];

    float* out     = (float*)d_out;
    float* z_out   = out;                                 // [NN, 128]
    float* h_out   = out + (size_t)NN * DOUT;             // [NN, 256]
    float* seq_out = h_out + (size_t)NN * DHID;           // [NN, 256]

    __half *pth, *phh, *pfh, *pw1, *pw23, *pfcw;
    float  *pon;
    cudaGetSymbolAddress((void**)&pth,  g_th);
    cudaGetSymbolAddress((void**)&phh,  g_hh);
    cudaGetSymbolAddress((void**)&pfh,  g_fh);
    cudaGetSymbolAddress((void**)&pw1,  g_w1h);
    cudaGetSymbolAddress((void**)&pw23, g_w23h);
    cudaGetSymbolAddress((void**)&pfcw, g_fcwh);
    cudaGetSymbolAddress((void**)&pon,  g_outnorm);

    const int T = 256;
    dim3 ggrid(2, (NN + 127) / 128);
    const int gather_blocks = (NN * 32 + T - 1) / T;

    // ---- fork: weight conversions + CSR prologue on side stream ----
    cudaEventRecord(g_res.e_fork, 0);
    cudaStreamWaitEvent(g_res.s_pre, g_res.e_fork, 0);
    k_conv_w1 <<<256, T, 0, g_res.s_pre>>>(W1);
    k_conv_fcw<<<256, T, 0, g_res.s_pre>>>(fcW);
    k_conv_w128<<<128, T, 0, g_res.s_pre>>>(W2, 0);
    k_conv_w128<<<128, T, 0, g_res.s_pre>>>(W3, 128);
    cudaEventRecord(g_res.e_w, g_res.s_pre);
    k_zero_counts<<<(NN + T - 1) / T, T, 0, g_res.s_pre>>>();
    k_degree<<<(NE + T - 1) / T, T, 0, g_res.s_pre>>>(src, dst);
    k_fin_norms<<<(NN + T - 1) / T, T, 0, g_res.s_pre>>>();
    k_scan_p1<<<SCAN_GRID, SCAN_B, 0, g_res.s_pre>>>();
    k_scan_p2<<<1, SCAN_B, 0, g_res.s_pre>>>();
    k_scan_p3<<<SCAN_GRID, SCAN_B, 0, g_res.s_pre>>>();
    k_csr_fill<<<(NE + T - 1) / T, T, 0, g_res.s_pre>>>(src, dst);
    cudaEventRecord(g_res.e_csr, g_res.s_pre);

    // ---- main: feature conversion, then gemm1 (fp16) ----
    k_conv_feat<<<(NN * (DIN / 4) + T - 1) / T, T>>>(features);
    cudaStreamWaitEvent(0, g_res.e_w, 0);
    k_gemm_f16<1><<<ggrid, T>>>(pfh, nullptr, pw1, pth, NN);
    cudaEventRecord(g_res.e_g1, 0);

    // ---- side: gemm3 (seq_fts, fp16 inputs) overlapping the gather/gemm2 chain ----
    cudaStreamWaitEvent(g_res.s_g3, g_res.e_g1, 0);
    k_gemm_f16<0><<<ggrid, T, 0, g_res.s_g3>>>(pfh, nullptr, pfcw, seq_out, NN);
    cudaEventRecord(g_res.e_g3, g_res.s_g3);

    // ---- main: join CSR, layer-1 aggregate, layer 2 ----
    cudaStreamWaitEvent(0, g_res.e_csr, 0);
    k_gather_h<<<gather_blocks, T>>>(pth, b1, h_out, phh);
    k_gemm_f16<1><<<ggrid, T>>>(phh, pon, pw23, pth, NN);
    k_gather_z<<<gather_blocks, T>>>(pth, b2, b3, noise, z_out);

    // ---- final join: seq_fts must be complete before graph end ----
    cudaStreamWaitEvent(0, g_res.e_g3, 0);
}

// round 12
// speedup vs baseline: 1.3702x; 1.0262x over previous
#include <cuda_runtime.h>
#include <cuda_fp16.h>
#include <cstdint>
#include <cstddef>

#define NN   50000
#define NE   800000
#define DIN  256
#define DHID 256
#define DOUT 128
#define MID  25088    // gather_h/gemm2 split point (multiple of 128)

#define SCAN_B 256
#define SCAN_GRID ((NN + SCAN_B - 1) / SCAN_B)   // 196

// ---------------- scratch (device globals; no allocation allowed) ----------------
__device__ float g_outnorm[NN];
__device__ float g_innorm[NN];
__device__ int   g_outc[NN];
__device__ int   g_inc[NN];
__device__ int   g_rowptr[NN + 1];
__device__ int   g_cursor[NN];
__device__ int   g_poff[SCAN_B];                 // block partial sums -> offsets
__device__ int   g_csrc[NE];                     // src node per CSR slot (by dst)
__device__ __half g_th[(size_t)NN * DHID];       // pre-agg features t (fp16)
__device__ __half g_hh[(size_t)NN * DHID];       // fp16 copy of h (gemm2 input)
__device__ __half g_fh[(size_t)NN * DIN];        // fp16 features
__device__ __half g_w1h[DIN * DHID];             // W1^T  [n][k] fp16
__device__ __half g_w23h[DHID * DHID];           // [W2|W3]^T [n][k] fp16
__device__ __half g_fcwh[DHID * DIN];            // fcW (already [n][k]) fp16

// ---------------- conversion kernels ----------------
__global__ void k_conv_feat(const float* __restrict__ f) {
    int i = blockIdx.x * blockDim.x + threadIdx.x;
    if (i >= NN * (DIN / 4)) return;
    float4 v = ((const float4*)f)[i];
    __half2 h0 = __float22half2_rn(make_float2(v.x, v.y));
    __half2 h1 = __float22half2_rn(make_float2(v.z, v.w));
    uint2 o;
    o.x = *(uint32_t*)&h0;
    o.y = *(uint32_t*)&h1;
    ((uint2*)g_fh)[i] = o;
}

// all weight conversions in one launch (196608 threads)
__global__ void k_conv_weights(const float* __restrict__ W1, const float* __restrict__ W2,
                               const float* __restrict__ W3, const float* __restrict__ fcW) {
    int t = blockIdx.x * blockDim.x + threadIdx.x;
    if (t < 65536) {                              // W1 -> g_w1h transposed
        int n = t >> 8, k = t & 255;
        g_w1h[t] = __float2half(W1[k * 256 + n]);
    } else if (t < 131072) {                      // fcW -> g_fcwh direct
        int i = t - 65536;
        g_fcwh[i] = __float2half(fcW[i]);
    } else {                                      // W2|W3 -> g_w23h transposed
        int i = t - 131072;                       // 0..65535
        int hs = i >> 15;                         // 0: W2, 1: W3
        int j = i & 32767;
        int n = j >> 8, k = j & 255;
        const float* S = hs ? W3 : W2;
        g_w23h[(size_t)(hs * 128 + n) * 256 + k] = __float2half(S[k * 128 + n]);
    }
}

// ---------------- degree / norm / CSR kernels ----------------
__global__ void k_zero_counts() {
    int i = blockIdx.x * blockDim.x + threadIdx.x;
    if (i < NN) { g_outc[i] = 0; g_inc[i] = 0; }
}

__global__ void k_degree(const int* __restrict__ src, const int* __restrict__ dst) {
    int e = blockIdx.x * blockDim.x + threadIdx.x;
    if (e < NE) {
        atomicAdd(&g_outc[src[e]], 1);
        atomicAdd(&g_inc[dst[e]], 1);
    }
}

__global__ void k_fin_norms() {
    int i = blockIdx.x * blockDim.x + threadIdx.x;
    if (i < NN) {
        g_outnorm[i] = rsqrtf(fmaxf((float)g_outc[i], 1.f));
        g_innorm[i]  = rsqrtf(fmaxf((float)g_inc[i], 1.f));
    }
}

// ---- 3-phase multi-block exclusive scan of g_inc -> g_rowptr / g_cursor ----
__global__ void k_scan_p1() {
    __shared__ int ws[8];
    int i = blockIdx.x * SCAN_B + threadIdx.x;
    int lane = threadIdx.x & 31, wid = threadIdx.x >> 5;
    int v = (i < NN) ? g_inc[i] : 0;
#pragma unroll
    for (int o = 16; o > 0; o >>= 1) v += __shfl_down_sync(0xffffffffu, v, o);
    if (lane == 0) ws[wid] = v;
    __syncthreads();
    if (wid == 0) {
        int s = (lane < 8) ? ws[lane] : 0;
#pragma unroll
        for (int o = 4; o > 0; o >>= 1) s += __shfl_down_sync(0xffffffffu, s, o);
        if (lane == 0) g_poff[blockIdx.x] = s;
    }
}

__global__ void k_scan_p2() {
    __shared__ int ws[8];
    int tid = threadIdx.x, lane = tid & 31, wid = tid >> 5;
    int v = (tid < SCAN_GRID) ? g_poff[tid] : 0;
    int x = v;
#pragma unroll
    for (int o = 1; o < 32; o <<= 1) {
        int y = __shfl_up_sync(0xffffffffu, x, o);
        if (lane >= o) x += y;
    }
    if (lane == 31) ws[wid] = x;
    __syncthreads();
    if (wid == 0 && lane < 8) {
        int s = ws[lane];
        int xs = s;
#pragma unroll
        for (int o = 1; o < 8; o <<= 1) {
            int y = __shfl_up_sync(0xffu, xs, o);
            if (lane >= o) xs += y;
        }
        ws[lane] = xs - s;
    }
    __syncthreads();
    g_poff[tid] = ws[wid] + x - v;
}

__global__ void k_scan_p3() {
    __shared__ int ws[8];
    int i = blockIdx.x * SCAN_B + threadIdx.x;
    int lane = threadIdx.x & 31, wid = threadIdx.x >> 5;
    int v = (i < NN) ? g_inc[i] : 0;
    int x = v;
#pragma unroll
    for (int o = 1; o < 32; o <<= 1) {
        int y = __shfl_up_sync(0xffffffffu, x, o);
        if (lane >= o) x += y;
    }
    if (lane == 31) ws[wid] = x;
    __syncthreads();
    if (wid == 0 && lane < 8) {
        int s = ws[lane];
        int xs = s;
#pragma unroll
        for (int o = 1; o < 8; o <<= 1) {
            int y = __shfl_up_sync(0xffu, xs, o);
            if (lane >= o) xs += y;
        }
        ws[lane] = xs - s;
    }
    __syncthreads();
    if (i < NN) {
        int excl = g_poff[blockIdx.x] + ws[wid] + x - v;
        g_rowptr[i] = excl;
        g_cursor[i] = excl;
    }
    if (blockIdx.x == 0 && threadIdx.x == 0) g_rowptr[NN] = NE;
}

__global__ void k_csr_fill(const int* __restrict__ src, const int* __restrict__ dst) {
    int e = blockIdx.x * blockDim.x + threadIdx.x;
    if (e < NE) {
        int pos = atomicAdd(&g_cursor[dst[e]], 1);
        g_csrc[pos] = src[e];
    }
}

// ---------------- fp16 gather SpMM + fused epilogues ----------------
__device__ __forceinline__ void acc8_f16(float* a, uint4 v, float s) {
    __half2 p0 = *(__half2*)&v.x;
    __half2 p1 = *(__half2*)&v.y;
    __half2 p2 = *(__half2*)&v.z;
    __half2 p3 = *(__half2*)&v.w;
    float2 f0 = __half22float2(p0);
    float2 f1 = __half22float2(p1);
    float2 f2 = __half22float2(p2);
    float2 f3 = __half22float2(p3);
    a[0] = fmaf(f0.x, s, a[0]); a[1] = fmaf(f0.y, s, a[1]);
    a[2] = fmaf(f1.x, s, a[2]); a[3] = fmaf(f1.y, s, a[3]);
    a[4] = fmaf(f2.x, s, a[4]); a[5] = fmaf(f2.y, s, a[5]);
    a[6] = fmaf(f3.x, s, a[6]); a[7] = fmaf(f3.y, s, a[7]);
}

// h = relu(in_norm * sum outnorm[src]*t[src] + b1) for nodes [n0, n1)
__global__ void k_gather_h(const __half* __restrict__ t, const float* __restrict__ b1,
                           float* __restrict__ h, __half* __restrict__ hh,
                           int n0, int n1) {
    int node = n0 + ((blockIdx.x * blockDim.x + threadIdx.x) >> 5);
    int lane = threadIdx.x & 31;
    if (node >= n1) return;
    int beg = g_rowptr[node], end = g_rowptr[node + 1];
    float a[8];
#pragma unroll
    for (int i = 0; i < 8; i++) a[i] = 0.f;
    int j = beg;
    for (; j + 1 < end; j += 2) {
        int s0 = g_csrc[j], s1 = g_csrc[j + 1];
        float on0 = g_outnorm[s0], on1 = g_outnorm[s1];
        uint4 v0 = ((const uint4*)(t + (size_t)s0 * DHID))[lane];
        uint4 v1 = ((const uint4*)(t + (size_t)s1 * DHID))[lane];
        acc8_f16(a, v0, on0);
        acc8_f16(a, v1, on1);
    }
    if (j < end) {
        int s0 = g_csrc[j];
        float on0 = g_outnorm[s0];
        uint4 v = ((const uint4*)(t + (size_t)s0 * DHID))[lane];
        acc8_f16(a, v, on0);
    }
    float s = g_innorm[node];
    const float* bp = b1 + lane * 8;
    float4 bb0 = *(const float4*)bp;
    float4 bb1 = *(const float4*)(bp + 4);
    float4 o0, o1;
    o0.x = fmaxf(fmaf(a[0], s, bb0.x), 0.f); o0.y = fmaxf(fmaf(a[1], s, bb0.y), 0.f);
    o0.z = fmaxf(fmaf(a[2], s, bb0.z), 0.f); o0.w = fmaxf(fmaf(a[3], s, bb0.w), 0.f);
    o1.x = fmaxf(fmaf(a[4], s, bb1.x), 0.f); o1.y = fmaxf(fmaf(a[5], s, bb1.y), 0.f);
    o1.z = fmaxf(fmaf(a[6], s, bb1.z), 0.f); o1.w = fmaxf(fmaf(a[7], s, bb1.w), 0.f);
    float* hp = h + (size_t)node * DHID + lane * 8;
    *(float4*)hp = o0;
    *(float4*)(hp + 4) = o1;
    __half2 q0 = __float22half2_rn(make_float2(o0.x, o0.y));
    __half2 q1 = __float22half2_rn(make_float2(o0.z, o0.w));
    __half2 q2 = __float22half2_rn(make_float2(o1.x, o1.y));
    __half2 q3 = __float22half2_rn(make_float2(o1.z, o1.w));
    uint4 q;
    q.x = *(uint32_t*)&q0; q.y = *(uint32_t*)&q1;
    q.z = *(uint32_t*)&q2; q.w = *(uint32_t*)&q3;
    ((uint4*)(hh + (size_t)node * DHID))[lane] = q;
}

// z = relu(mean*in + b2) + noise * exp(logstd*in + b3)
__global__ void k_gather_z(const __half* __restrict__ t,
                           const float* __restrict__ b2, const float* __restrict__ b3,
                           const float* __restrict__ noise, float* __restrict__ z) {
    int node = (blockIdx.x * blockDim.x + threadIdx.x) >> 5;
    int lane = threadIdx.x & 31;
    if (node >= NN) return;
    int beg = g_rowptr[node], end = g_rowptr[node + 1];
    float a[8];
#pragma unroll
    for (int i = 0; i < 8; i++) a[i] = 0.f;
    int j = beg;
    for (; j + 1 < end; j += 2) {
        int s0 = g_csrc[j], s1 = g_csrc[j + 1];
        uint4 v0 = ((const uint4*)(t + (size_t)s0 * DHID))[lane];
        uint4 v1 = ((const uint4*)(t + (size_t)s1 * DHID))[lane];
        acc8_f16(a, v0, 1.f);
        acc8_f16(a, v1, 1.f);
    }
    if (j < end) {
        uint4 v = ((const uint4*)(t + (size_t)g_csrc[j] * DHID))[lane];
        acc8_f16(a, v, 1.f);
    }
    float l[8];
#pragma unroll
    for (int i = 0; i < 8; i++) l[i] = __shfl_down_sync(0xffffffffu, a[i], 16);
    if (lane < 16) {
        float s = g_innorm[node];
        const float* bmp = b2 + lane * 8;
        const float* blp = b3 + lane * 8;
        const float* nvp = noise + (size_t)node * DOUT + lane * 8;
        float4 bm0 = *(const float4*)bmp,        bm1 = *(const float4*)(bmp + 4);
        float4 bl0 = *(const float4*)blp,        bl1 = *(const float4*)(blp + 4);
        float4 n0  = *(const float4*)nvp,        n1  = *(const float4*)(nvp + 4);
        float4 r0, r1;
        r0.x = fmaxf(fmaf(a[0], s, bm0.x), 0.f) + n0.x * expf(fmaf(l[0], s, bl0.x));
        r0.y = fmaxf(fmaf(a[1], s, bm0.y), 0.f) + n0.y * expf(fmaf(l[1], s, bl0.y));
        r0.z = fmaxf(fmaf(a[2], s, bm0.z), 0.f) + n0.z * expf(fmaf(l[2], s, bl0.z));
        r0.w = fmaxf(fmaf(a[3], s, bm0.w), 0.f) + n0.w * expf(fmaf(l[3], s, bl0.w));
        r1.x = fmaxf(fmaf(a[4], s, bm1.x), 0.f) + n1.x * expf(fmaf(l[4], s, bl1.x));
        r1.y = fmaxf(fmaf(a[5], s, bm1.y), 0.f) + n1.y * expf(fmaf(l[5], s, bl1.y));
        r1.z = fmaxf(fmaf(a[6], s, bm1.z), 0.f) + n1.z * expf(fmaf(l[6], s, bl1.z));
        r1.w = fmaxf(fmaf(a[7], s, bm1.w), 0.f) + n1.w * expf(fmaf(l[7], s, bl1.w));
        float* zp = z + (size_t)node * DOUT + lane * 8;
        *(float4*)zp = r0;
        *(float4*)(zp + 4) = r1;
    }
}

// ---------------- fp16 mma / cp.async helpers ----------------
__device__ __forceinline__ void mma_f16(float* c, const uint32_t* a, const uint32_t* b) {
    asm volatile(
        "mma.sync.aligned.m16n8k16.row.col.f32.f16.f16.f32 "
        "{%0,%1,%2,%3}, {%4,%5,%6,%7}, {%8,%9}, {%0,%1,%2,%3};"
        : "+f"(c[0]), "+f"(c[1]), "+f"(c[2]), "+f"(c[3])
        : "r"(a[0]), "r"(a[1]), "r"(a[2]), "r"(a[3]), "r"(b[0]), "r"(b[1]));
}

__device__ __forceinline__ void cp16(uint32_t dst, const void* src) {
    asm volatile("cp.async.cg.shared.global [%0], [%1], 16;" :: "r"(dst), "l"(src));
}
__device__ __forceinline__ void cp_commit() { asm volatile("cp.async.commit_group;"); }
template<int N>
__device__ __forceinline__ void cp_wait() { asm volatile("cp.async.wait_group %0;" :: "n"(N)); }

// ---------------- fp16 tensor-core GEMM (3-stage cp.async pipeline) ----------------
// C[M][256] = A[M][256](fp16, K-contig) @ B[256][256](fp16, [n][k]) ; * rowscale on rows
template<int OUTHALF>
__global__ void __launch_bounds__(256, 2)
k_gemm_f16(const __half* __restrict__ A, const float* __restrict__ rowscale,
           const __half* __restrict__ B, void* __restrict__ Cv, int M)
{
    constexpr int K = 256, NCOLS = 256;
    constexpr int BM = 128, BN = 128, BK = 32;
    constexpr int ALD = 40;                       // halfs per smem row (80B)
    constexpr int ST = 3;
    __shared__ __align__(16) __half As[ST][BM * ALD];
    __shared__ __align__(16) __half Bs[ST][BN * ALD];

    const int tid  = threadIdx.x;
    const int lane = tid & 31;
    const int warp = tid >> 5;
    const int row0 = blockIdx.y * BM;
    const int col0 = blockIdx.x * BN;
    const int warpM = (warp >> 2) * 64;
    const int warpN = (warp & 3) * 32;

    float acc[4][4][4];
#pragma unroll
    for (int i = 0; i < 4; i++)
#pragma unroll
        for (int j = 0; j < 4; j++)
#pragma unroll
            for (int r = 0; r < 4; r++) acc[i][j][r] = 0.f;

    auto stage = [&](int k0, int buf) {
#pragma unroll
        for (int i = 0; i < 2; i++) {
            int c = tid * 2 + i;                  // 512 chunks of 16B
            int r = c >> 2;
            int off = (c & 3) * 8;                // halfs
            int gr = row0 + r;
            if (gr >= M) gr = M - 1;
            cp16((uint32_t)__cvta_generic_to_shared(&As[buf][r * ALD + off]),
                 A + (size_t)gr * K + k0 + off);
            cp16((uint32_t)__cvta_generic_to_shared(&Bs[buf][r * ALD + off]),
                 B + (size_t)(col0 + r) * K + k0 + off);
        }
    };

    const int NT = K / BK;                        // 8
    stage(0, 0);
    cp_commit();
    stage(BK, 1);
    cp_commit();

    for (int t = 0; t < NT; t++) {
        int buf = t % ST;
        if (t < NT - 1) cp_wait<1>(); else cp_wait<0>();
        __syncthreads();
        if (t + 2 < NT) {
            stage((t + 2) * BK, (t + 2) % ST);
            cp_commit();
        }

#pragma unroll
        for (int ks = 0; ks < 2; ks++) {
            const int kb = ks * 16 + (lane & 3) * 2;
            uint32_t a[4][4], b[4][2];
#pragma unroll
            for (int mi = 0; mi < 4; mi++) {
                const __half* ap = &As[buf][(warpM + mi * 16 + (lane >> 2)) * ALD + kb];
                a[mi][0] = *(const uint32_t*)ap;
                a[mi][1] = *(const uint32_t*)(ap + 8 * ALD);
                a[mi][2] = *(const uint32_t*)(ap + 8);
                a[mi][3] = *(const uint32_t*)(ap + 8 * ALD + 8);
            }
#pragma unroll
            for (int ni = 0; ni < 4; ni++) {
                const __half* bp = &Bs[buf][(warpN + ni * 8 + (lane >> 2)) * ALD + kb];
                b[ni][0] = *(const uint32_t*)bp;
                b[ni][1] = *(const uint32_t*)(bp + 8);
            }
#pragma unroll
            for (int mi = 0; mi < 4; mi++)
#pragma unroll
                for (int ni = 0; ni < 4; ni++)
                    mma_f16(acc[mi][ni], a[mi], b[ni]);
        }
    }

    // epilogue: rowscale + store
#pragma unroll
    for (int mi = 0; mi < 4; mi++) {
        int gr0 = row0 + warpM + mi * 16 + (lane >> 2);
        float s0 = 1.f, s1 = 1.f;
        if (rowscale) {
            if (gr0 < M)     s0 = rowscale[gr0];
            if (gr0 + 8 < M) s1 = rowscale[gr0 + 8];
        }
#pragma unroll
        for (int ni = 0; ni < 4; ni++) {
            int col = col0 + warpN + ni * 8 + (lane & 3) * 2;
            if constexpr (OUTHALF) {
                __half* Ch = (__half*)Cv;
                if (gr0 < M)
                    *(__half2*)(Ch + (size_t)gr0 * NCOLS + col) =
                        __float22half2_rn(make_float2(acc[mi][ni][0] * s0, acc[mi][ni][1] * s0));
                if (gr0 + 8 < M)
                    *(__half2*)(Ch + (size_t)(gr0 + 8) * NCOLS + col) =
                        __float22half2_rn(make_float2(acc[mi][ni][2] * s1, acc[mi][ni][3] * s1));
            } else {
                float* C = (float*)Cv;
                if (gr0 < M)
                    *(float2*)(C + (size_t)gr0 * NCOLS + col) =
                        make_float2(acc[mi][ni][0] * s0, acc[mi][ni][1] * s0);
                if (gr0 + 8 < M)
                    *(float2*)(C + (size_t)(gr0 + 8) * NCOLS + col) =
                        make_float2(acc[mi][ni][2] * s1, acc[mi][ni][3] * s1);
            }
        }
    }
}

// ---------------- stream/event singletons (host resources, created once) ----------
namespace {
struct HxRes {
    cudaStream_t s_pre = nullptr, s_g3 = nullptr, s_g2 = nullptr;
    cudaEvent_t  e_fork = nullptr, e_w = nullptr, e_csr = nullptr,
                 e_g1 = nullptr, e_g3 = nullptr, e_gh1 = nullptr, e_g2 = nullptr;
    HxRes() {
        cudaStreamCreateWithFlags(&s_pre, cudaStreamNonBlocking);
        cudaStreamCreateWithFlags(&s_g3,  cudaStreamNonBlocking);
        cudaStreamCreateWithFlags(&s_g2,  cudaStreamNonBlocking);
        cudaEventCreateWithFlags(&e_fork, cudaEventDisableTiming);
        cudaEventCreateWithFlags(&e_w,    cudaEventDisableTiming);
        cudaEventCreateWithFlags(&e_csr,  cudaEventDisableTiming);
        cudaEventCreateWithFlags(&e_g1,   cudaEventDisableTiming);
        cudaEventCreateWithFlags(&e_g3,   cudaEventDisableTiming);
        cudaEventCreateWithFlags(&e_gh1,  cudaEventDisableTiming);
        cudaEventCreateWithFlags(&e_g2,   cudaEventDisableTiming);
    }
};
HxRes g_res;
}

// ---------------- launch ----------------
extern "C" void kernel_launch(void* const* d_in, const int* in_sizes, int n_in,
                              void* d_out, int out_size)
{
    const float* features = (const float*)d_in[0];
    const float* noise    = (const float*)d_in[1];
    const float* W1       = (const float*)d_in[2];
    const float* b1       = (const float*)d_in[3];
    const float* W2       = (const float*)d_in[4];
    const float* b2       = (const float*)d_in[5];
    const float* W3       = (const float*)d_in[6];
    const float* b3       = (const float*)d_in[7];
    const float* fcW      = (const float*)d_in[8];
    const int*   src      = (const int*)d_in[9];
    const int*   dst      = (const int*)d_in[10];

    float* out     = (float*)d_out;
    float* z_out   = out;                                 // [NN, 128]
    float* h_out   = out + (size_t)NN * DOUT;             // [NN, 256]
    float* seq_out = h_out + (size_t)NN * DHID;           // [NN, 256]

    __half *pth, *phh, *pfh, *pw1, *pw23, *pfcw;
    float  *pon;
    cudaGetSymbolAddress((void**)&pth,  g_th);
    cudaGetSymbolAddress((void**)&phh,  g_hh);
    cudaGetSymbolAddress((void**)&pfh,  g_fh);
    cudaGetSymbolAddress((void**)&pw1,  g_w1h);
    cudaGetSymbolAddress((void**)&pw23, g_w23h);
    cudaGetSymbolAddress((void**)&pfcw, g_fcwh);
    cudaGetSymbolAddress((void**)&pon,  g_outnorm);

    const int T = 256;
    dim3 ggrid(2, (NN + 127) / 128);
    dim3 ggrid_lo(2, MID / 128);
    dim3 ggrid_hi(2, (NN - MID + 127) / 128);

    // ---- fork: weight conversion + CSR prologue on side stream ----
    cudaEventRecord(g_res.e_fork, 0);
    cudaStreamWaitEvent(g_res.s_pre, g_res.e_fork, 0);
    k_conv_weights<<<768, T, 0, g_res.s_pre>>>(W1, W2, W3, fcW);
    cudaEventRecord(g_res.e_w, g_res.s_pre);
    k_zero_counts<<<(NN + T - 1) / T, T, 0, g_res.s_pre>>>();
    k_degree<<<(NE + T - 1) / T, T, 0, g_res.s_pre>>>(src, dst);
    k_fin_norms<<<(NN + T - 1) / T, T, 0, g_res.s_pre>>>();
    k_scan_p1<<<SCAN_GRID, SCAN_B, 0, g_res.s_pre>>>();
    k_scan_p2<<<1, SCAN_B, 0, g_res.s_pre>>>();
    k_scan_p3<<<SCAN_GRID, SCAN_B, 0, g_res.s_pre>>>();
    k_csr_fill<<<(NE + T - 1) / T, T, 0, g_res.s_pre>>>(src, dst);
    cudaEventRecord(g_res.e_csr, g_res.s_pre);

    // ---- main: feature conversion, then gemm1 (fp16) ----
    k_conv_feat<<<(NN * (DIN / 4) + T - 1) / T, T>>>(features);
    cudaStreamWaitEvent(0, g_res.e_w, 0);
    k_gemm_f16<1><<<ggrid, T>>>(pfh, nullptr, pw1, pth, NN);
    cudaEventRecord(g_res.e_g1, 0);

    // ---- side: gemm3 (seq_fts) after gemm1, overlapping the rest ----
    cudaStreamWaitEvent(g_res.s_g3, g_res.e_g1, 0);
    k_gemm_f16<0><<<ggrid, T, 0, g_res.s_g3>>>(pfh, nullptr, pfcw, seq_out, NN);
    cudaEventRecord(g_res.e_g3, g_res.s_g3);

    // ---- main: join CSR; gather_h split into halves ----
    cudaStreamWaitEvent(0, g_res.e_csr, 0);
    k_gather_h<<<(MID * 32 + T - 1) / T, T>>>(pth, b1, h_out, phh, 0, MID);
    cudaEventRecord(g_res.e_gh1, 0);
    k_gather_h<<<((NN - MID) * 32 + T - 1) / T, T>>>(pth, b1, h_out, phh, MID, NN);

    // ---- side: gemm2 lower half overlaps gather_h upper half ----
    cudaStreamWaitEvent(g_res.s_g2, g_res.e_gh1, 0);
    k_gemm_f16<1><<<ggrid_lo, T, 0, g_res.s_g2>>>(phh, pon, pw23, pth, MID);
    cudaEventRecord(g_res.e_g2, g_res.s_g2);

    // ---- main: gemm2 upper half, join lower, gather_z ----
    k_gemm_f16<1><<<ggrid_hi, T>>>(phh + (size_t)MID * DHID, pon + MID, pw23,
                                   pth + (size_t)MID * DHID, NN - MID);
    cudaStreamWaitEvent(0, g_res.e_g2, 0);
    k_gather_z<<<(NN * 32 + T - 1) / T, T>>>(pth, b2, b3, noise, z_out);

    // ---- final join: seq_fts must be complete before graph end ----
    cudaStreamWaitEvent(0, g_res.e_g3, 0);
}

// round 13
// speedup vs baseline: 1.3935x; 1.0170x over previous
#include <cuda_runtime.h>
#include <cuda_fp16.h>
#include <cstdint>
#include <cstddef>

#define NN   50000
#define NE   800000
#define DIN  256
#define DHID 256
#define DOUT 128
#define MID  25088    // gather_h/gemm2 split point (multiple of 128)

#define SCAN_B 256
#define SCAN_GRID ((NN + SCAN_B - 1) / SCAN_B)   // 196

// ---------------- scratch (device globals; no allocation allowed) ----------------
// g_outc/g_inc rely on zero-initialization at module load; every call re-zeroes
// them at its tail (shadowed), so each invocation starts from zeros.
__device__ float g_outnorm[NN];
__device__ float g_innorm[NN];
__device__ int   g_outc[NN];
__device__ int   g_inc[NN];
__device__ int   g_rowptr[NN + 1];
__device__ int   g_cursor[NN];
__device__ int   g_poff[SCAN_B];                 // per-block inc sums
__device__ int   g_csrc[NE];                     // src node per CSR slot (by dst)
__device__ __half g_th[(size_t)NN * DHID];       // pre-agg features t (fp16)
__device__ __half g_hh[(size_t)NN * DHID];       // fp16 copy of h (gemm2 input)
__device__ __half g_fh[(size_t)NN * DIN];        // fp16 features
__device__ __half g_w1h[DIN * DHID];             // W1^T  [n][k] fp16
__device__ __half g_w23h[DHID * DHID];           // [W2|W3]^T [n][k] fp16
__device__ __half g_fcwh[DHID * DIN];            // fcW (already [n][k]) fp16

// ---------------- conversion kernels ----------------
__global__ void k_conv_feat(const float* __restrict__ f) {
    int i = blockIdx.x * blockDim.x + threadIdx.x;
    if (i >= NN * (DIN / 4)) return;
    float4 v = ((const float4*)f)[i];
    __half2 h0 = __float22half2_rn(make_float2(v.x, v.y));
    __half2 h1 = __float22half2_rn(make_float2(v.z, v.w));
    uint2 o;
    o.x = *(uint32_t*)&h0;
    o.y = *(uint32_t*)&h1;
    ((uint2*)g_fh)[i] = o;
}

// all weight conversions in one launch (196608 threads)
__global__ void k_conv_weights(const float* __restrict__ W1, const float* __restrict__ W2,
                               const float* __restrict__ W3, const float* __restrict__ fcW) {
    int t = blockIdx.x * blockDim.x + threadIdx.x;
    if (t < 65536) {                              // W1 -> g_w1h transposed
        int n = t >> 8, k = t & 255;
        g_w1h[t] = __float2half(W1[k * 256 + n]);
    } else if (t < 131072) {                      // fcW -> g_fcwh direct
        int i = t - 65536;
        g_fcwh[i] = __float2half(fcW[i]);
    } else {                                      // W2|W3 -> g_w23h transposed
        int i = t - 131072;                       // 0..65535
        int hs = i >> 15;                         // 0: W2, 1: W3
        int j = i & 32767;
        int n = j >> 8, k = j & 255;
        const float* S = hs ? W3 : W2;
        g_w23h[(size_t)(hs * 128 + n) * 256 + k] = __float2half(S[k * 128 + n]);
    }
}

// ---------------- degree / norm / CSR kernels ----------------
// 2 edges per thread
__global__ void k_degree(const int* __restrict__ src, const int* __restrict__ dst) {
    int e = (blockIdx.x * blockDim.x + threadIdx.x) * 2;
    if (e + 1 < NE) {
        int2 s = *(const int2*)(src + e);
        int2 d = *(const int2*)(dst + e);
        atomicAdd(&g_outc[s.x], 1);
        atomicAdd(&g_outc[s.y], 1);
        atomicAdd(&g_inc[d.x], 1);
        atomicAdd(&g_inc[d.y], 1);
    } else if (e < NE) {
        atomicAdd(&g_outc[src[e]], 1);
        atomicAdd(&g_inc[dst[e]], 1);
    }
}

// tail zeroing (runs shadowed at graph end; restores zero-state for next replay)
__global__ void k_zero_counts() {
    int i = blockIdx.x * blockDim.x + threadIdx.x;
    if (i < NN) { g_outc[i] = 0; g_inc[i] = 0; }
}

// phase 1 (fused with norms): per-block inc sums + out/in norms
__global__ void k_scan_p1n() {
    __shared__ int ws[8];
    int i = blockIdx.x * SCAN_B + threadIdx.x;
    int lane = threadIdx.x & 31, wid = threadIdx.x >> 5;
    int v = 0;
    if (i < NN) {
        int oc = g_outc[i];
        v = g_inc[i];
        g_outnorm[i] = rsqrtf(fmaxf((float)oc, 1.f));
        g_innorm[i]  = rsqrtf(fmaxf((float)v, 1.f));
    }
    int x = v;
#pragma unroll
    for (int o = 16; o > 0; o >>= 1) x += __shfl_down_sync(0xffffffffu, x, o);
    if (lane == 0) ws[wid] = x;
    __syncthreads();
    if (wid == 0) {
        int s = (lane < 8) ? ws[lane] : 0;
#pragma unroll
        for (int o = 4; o > 0; o >>= 1) s += __shfl_down_sync(0xffffffffu, s, o);
        if (lane == 0) g_poff[blockIdx.x] = s;
    }
}

// phase 2+3 fused: each block computes its own global offset by reducing
// g_poff[0..b) (<=196 values), then local exclusive scan -> rowptr/cursor.
__global__ void k_scan_p3f() {
    __shared__ int ws[8];
    __shared__ int s_off;
    const int b = blockIdx.x;
    int tid = threadIdx.x, lane = tid & 31, wid = tid >> 5;

    // block offset = sum of partials before b
    int p = (tid < b && tid < SCAN_GRID) ? g_poff[tid] : 0;
#pragma unroll
    for (int o = 16; o > 0; o >>= 1) p += __shfl_down_sync(0xffffffffu, p, o);
    if (lane == 0) ws[wid] = p;
    __syncthreads();
    if (wid == 0) {
        int s = (lane < 8) ? ws[lane] : 0;
#pragma unroll
        for (int o = 4; o > 0; o >>= 1) s += __shfl_down_sync(0xffffffffu, s, o);
        if (lane == 0) s_off = s;
    }
    __syncthreads();

    // local exclusive scan of this block's g_inc chunk
    int i = b * SCAN_B + tid;
    int v = (i < NN) ? g_inc[i] : 0;
    int x = v;
#pragma unroll
    for (int o = 1; o < 32; o <<= 1) {
        int y = __shfl_up_sync(0xffffffffu, x, o);
        if (lane >= o) x += y;
    }
    __syncthreads();
    if (lane == 31) ws[wid] = x;
    __syncthreads();
    if (wid == 0 && lane < 8) {
        int s = ws[lane];
        int xs = s;
#pragma unroll
        for (int o = 1; o < 8; o <<= 1) {
            int y = __shfl_up_sync(0xffu, xs, o);
            if (lane >= o) xs += y;
        }
        ws[lane] = xs - s;
    }
    __syncthreads();
    if (i < NN) {
        int excl = s_off + ws[wid] + x - v;
        g_rowptr[i] = excl;
        g_cursor[i] = excl;
    }
    if (b == 0 && tid == 0) g_rowptr[NN] = NE;
}

__global__ void k_csr_fill(const int* __restrict__ src, const int* __restrict__ dst) {
    int e = blockIdx.x * blockDim.x + threadIdx.x;
    if (e < NE) {
        int pos = atomicAdd(&g_cursor[dst[e]], 1);
        g_csrc[pos] = src[e];
    }
}

// ---------------- fp16 gather SpMM + fused epilogues ----------------
__device__ __forceinline__ void acc8_f16(float* a, uint4 v, float s) {
    __half2 p0 = *(__half2*)&v.x;
    __half2 p1 = *(__half2*)&v.y;
    __half2 p2 = *(__half2*)&v.z;
    __half2 p3 = *(__half2*)&v.w;
    float2 f0 = __half22float2(p0);
    float2 f1 = __half22float2(p1);
    float2 f2 = __half22float2(p2);
    float2 f3 = __half22float2(p3);
    a[0] = fmaf(f0.x, s, a[0]); a[1] = fmaf(f0.y, s, a[1]);
    a[2] = fmaf(f1.x, s, a[2]); a[3] = fmaf(f1.y, s, a[3]);
    a[4] = fmaf(f2.x, s, a[4]); a[5] = fmaf(f2.y, s, a[5]);
    a[6] = fmaf(f3.x, s, a[6]); a[7] = fmaf(f3.y, s, a[7]);
}

// h = relu(in_norm * sum outnorm[src]*t[src] + b1) for nodes [n0, n1)
__global__ void k_gather_h(const __half* __restrict__ t, const float* __restrict__ b1,
                           float* __restrict__ h, __half* __restrict__ hh,
                           int n0, int n1) {
    int node = n0 + ((blockIdx.x * blockDim.x + threadIdx.x) >> 5);
    int lane = threadIdx.x & 31;
    if (node >= n1) return;
    int beg = g_rowptr[node], end = g_rowptr[node + 1];
    float a[8];
#pragma unroll
    for (int i = 0; i < 8; i++) a[i] = 0.f;
    int j = beg;
    for (; j + 1 < end; j += 2) {
        int s0 = g_csrc[j], s1 = g_csrc[j + 1];
        float on0 = g_outnorm[s0], on1 = g_outnorm[s1];
        uint4 v0 = ((const uint4*)(t + (size_t)s0 * DHID))[lane];
        uint4 v1 = ((const uint4*)(t + (size_t)s1 * DHID))[lane];
        acc8_f16(a, v0, on0);
        acc8_f16(a, v1, on1);
    }
    if (j < end) {
        int s0 = g_csrc[j];
        float on0 = g_outnorm[s0];
        uint4 v = ((const uint4*)(t + (size_t)s0 * DHID))[lane];
        acc8_f16(a, v, on0);
    }
    float s = g_innorm[node];
    const float* bp = b1 + lane * 8;
    float4 bb0 = *(const float4*)bp;
    float4 bb1 = *(const float4*)(bp + 4);
    float4 o0, o1;
    o0.x = fmaxf(fmaf(a[0], s, bb0.x), 0.f); o0.y = fmaxf(fmaf(a[1], s, bb0.y), 0.f);
    o0.z = fmaxf(fmaf(a[2], s, bb0.z), 0.f); o0.w = fmaxf(fmaf(a[3], s, bb0.w), 0.f);
    o1.x = fmaxf(fmaf(a[4], s, bb1.x), 0.f); o1.y = fmaxf(fmaf(a[5], s, bb1.y), 0.f);
    o1.z = fmaxf(fmaf(a[6], s, bb1.z), 0.f); o1.w = fmaxf(fmaf(a[7], s, bb1.w), 0.f);
    float* hp = h + (size_t)node * DHID + lane * 8;
    *(float4*)hp = o0;
    *(float4*)(hp + 4) = o1;
    __half2 q0 = __float22half2_rn(make_float2(o0.x, o0.y));
    __half2 q1 = __float22half2_rn(make_float2(o0.z, o0.w));
    __half2 q2 = __float22half2_rn(make_float2(o1.x, o1.y));
    __half2 q3 = __float22half2_rn(make_float2(o1.z, o1.w));
    uint4 q;
    q.x = *(uint32_t*)&q0; q.y = *(uint32_t*)&q1;
    q.z = *(uint32_t*)&q2; q.w = *(uint32_t*)&q3;
    ((uint4*)(hh + (size_t)node * DHID))[lane] = q;
}

// z = relu(mean*in + b2) + noise * exp(logstd*in + b3)
__global__ void k_gather_z(const __half* __restrict__ t,
                           const float* __restrict__ b2, const float* __restrict__ b3,
                           const float* __restrict__ noise, float* __restrict__ z) {
    int node = (blockIdx.x * blockDim.x + threadIdx.x) >> 5;
    int lane = threadIdx.x & 31;
    if (node >= NN) return;
    int beg = g_rowptr[node], end = g_rowptr[node + 1];
    float a[8];
#pragma unroll
    for (int i = 0; i < 8; i++) a[i] = 0.f;
    int j = beg;
    for (; j + 1 < end; j += 2) {
        int s0 = g_csrc[j], s1 = g_csrc[j + 1];
        uint4 v0 = ((const uint4*)(t + (size_t)s0 * DHID))[lane];
        uint4 v1 = ((const uint4*)(t + (size_t)s1 * DHID))[lane];
        acc8_f16(a, v0, 1.f);
        acc8_f16(a, v1, 1.f);
    }
    if (j < end) {
        uint4 v = ((const uint4*)(t + (size_t)g_csrc[j] * DHID))[lane];
        acc8_f16(a, v, 1.f);
    }
    float l[8];
#pragma unroll
    for (int i = 0; i < 8; i++) l[i] = __shfl_down_sync(0xffffffffu, a[i], 16);
    if (lane < 16) {
        float s = g_innorm[node];
        const float* bmp = b2 + lane * 8;
        const float* blp = b3 + lane * 8;
        const float* nvp = noise + (size_t)node * DOUT + lane * 8;
        float4 bm0 = *(const float4*)bmp,        bm1 = *(const float4*)(bmp + 4);
        float4 bl0 = *(const float4*)blp,        bl1 = *(const float4*)(blp + 4);
        float4 n0  = *(const float4*)nvp,        n1  = *(const float4*)(nvp + 4);
        float4 r0, r1;
        r0.x = fmaxf(fmaf(a[0], s, bm0.x), 0.f) + n0.x * expf(fmaf(l[0], s, bl0.x));
        r0.y = fmaxf(fmaf(a[1], s, bm0.y), 0.f) + n0.y * expf(fmaf(l[1], s, bl0.y));
        r0.z = fmaxf(fmaf(a[2], s, bm0.z), 0.f) + n0.z * expf(fmaf(l[2], s, bl0.z));
        r0.w = fmaxf(fmaf(a[3], s, bm0.w), 0.f) + n0.w * expf(fmaf(l[3], s, bl0.w));
        r1.x = fmaxf(fmaf(a[4], s, bm1.x), 0.f) + n1.x * expf(fmaf(l[4], s, bl1.x));
        r1.y = fmaxf(fmaf(a[5], s, bm1.y), 0.f) + n1.y * expf(fmaf(l[5], s, bl1.y));
        r1.z = fmaxf(fmaf(a[6], s, bm1.z), 0.f) + n1.z * expf(fmaf(l[6], s, bl1.z));
        r1.w = fmaxf(fmaf(a[7], s, bm1.w), 0.f) + n1.w * expf(fmaf(l[7], s, bl1.w));
        float* zp = z + (size_t)node * DOUT + lane * 8;
        *(float4*)zp = r0;
        *(float4*)(zp + 4) = r1;
    }
}

// ---------------- fp16 mma / cp.async helpers ----------------
__device__ __forceinline__ void mma_f16(float* c, const uint32_t* a, const uint32_t* b) {
    asm volatile(
        "mma.sync.aligned.m16n8k16.row.col.f32.f16.f16.f32 "
        "{%0,%1,%2,%3}, {%4,%5,%6,%7}, {%8,%9}, {%0,%1,%2,%3};"
        : "+f"(c[0]), "+f"(c[1]), "+f"(c[2]), "+f"(c[3])
        : "r"(a[0]), "r"(a[1]), "r"(a[2]), "r"(a[3]), "r"(b[0]), "r"(b[1]));
}

__device__ __forceinline__ void cp16(uint32_t dst, const void* src) {
    asm volatile("cp.async.cg.shared.global [%0], [%1], 16;" :: "r"(dst), "l"(src));
}
__device__ __forceinline__ void cp_commit() { asm volatile("cp.async.commit_group;"); }
template<int N>
__device__ __forceinline__ void cp_wait() { asm volatile("cp.async.wait_group %0;" :: "n"(N)); }

// ---------------- fp16 tensor-core GEMM (3-stage cp.async pipeline) ----------------
template<int OUTHALF>
__global__ void __launch_bounds__(256, 2)
k_gemm_f16(const __half* __restrict__ A, const float* __restrict__ rowscale,
           const __half* __restrict__ B, void* __restrict__ Cv, int M)
{
    constexpr int K = 256, NCOLS = 256;
    constexpr int BM = 128, BN = 128, BK = 32;
    constexpr int ALD = 40;
    constexpr int ST = 3;
    __shared__ __align__(16) __half As[ST][BM * ALD];
    __shared__ __align__(16) __half Bs[ST][BN * ALD];

    const int tid  = threadIdx.x;
    const int lane = tid & 31;
    const int warp = tid >> 5;
    const int row0 = blockIdx.y * BM;
    const int col0 = blockIdx.x * BN;
    const int warpM = (warp >> 2) * 64;
    const int warpN = (warp & 3) * 32;

    float acc[4][4][4];
#pragma unroll
    for (int i = 0; i < 4; i++)
#pragma unroll
        for (int j = 0; j < 4; j++)
#pragma unroll
            for (int r = 0; r < 4; r++) acc[i][j][r] = 0.f;

    auto stage = [&](int k0, int buf) {
#pragma unroll
        for (int i = 0; i < 2; i++) {
            int c = tid * 2 + i;
            int r = c >> 2;
            int off = (c & 3) * 8;
            int gr = row0 + r;
            if (gr >= M) gr = M - 1;
            cp16((uint32_t)__cvta_generic_to_shared(&As[buf][r * ALD + off]),
                 A + (size_t)gr * K + k0 + off);
            cp16((uint32_t)__cvta_generic_to_shared(&Bs[buf][r * ALD + off]),
                 B + (size_t)(col0 + r) * K + k0 + off);
        }
    };

    const int NT = K / BK;
    stage(0, 0);
    cp_commit();
    stage(BK, 1);
    cp_commit();

    for (int t = 0; t < NT; t++) {
        int buf = t % ST;
        if (t < NT - 1) cp_wait<1>(); else cp_wait<0>();
        __syncthreads();
        if (t + 2 < NT) {
            stage((t + 2) * BK, (t + 2) % ST);
            cp_commit();
        }

#pragma unroll
        for (int ks = 0; ks < 2; ks++) {
            const int kb = ks * 16 + (lane & 3) * 2;
            uint32_t a[4][4], b[4][2];
#pragma unroll
            for (int mi = 0; mi < 4; mi++) {
                const __half* ap = &As[buf][(warpM + mi * 16 + (lane >> 2)) * ALD + kb];
                a[mi][0] = *(const uint32_t*)ap;
                a[mi][1] = *(const uint32_t*)(ap + 8 * ALD);
                a[mi][2] = *(const uint32_t*)(ap + 8);
                a[mi][3] = *(const uint32_t*)(ap + 8 * ALD + 8);
            }
#pragma unroll
            for (int ni = 0; ni < 4; ni++) {
                const __half* bp = &Bs[buf][(warpN + ni * 8 + (lane >> 2)) * ALD + kb];
                b[ni][0] = *(const uint32_t*)bp;
                b[ni][1] = *(const uint32_t*)(bp + 8);
            }
#pragma unroll
            for (int mi = 0; mi < 4; mi++)
#pragma unroll
                for (int ni = 0; ni < 4; ni++)
                    mma_f16(acc[mi][ni], a[mi], b[ni]);
        }
    }

#pragma unroll
    for (int mi = 0; mi < 4; mi++) {
        int gr0 = row0 + warpM + mi * 16 + (lane >> 2);
        float s0 = 1.f, s1 = 1.f;
        if (rowscale) {
            if (gr0 < M)     s0 = rowscale[gr0];
            if (gr0 + 8 < M) s1 = rowscale[gr0 + 8];
        }
#pragma unroll
        for (int ni = 0; ni < 4; ni++) {
            int col = col0 + warpN + ni * 8 + (lane & 3) * 2;
            if constexpr (OUTHALF) {
                __half* Ch = (__half*)Cv;
                if (gr0 < M)
                    *(__half2*)(Ch + (size_t)gr0 * NCOLS + col) =
                        __float22half2_rn(make_float2(acc[mi][ni][0] * s0, acc[mi][ni][1] * s0));
                if (gr0 + 8 < M)
                    *(__half2*)(Ch + (size_t)(gr0 + 8) * NCOLS + col) =
                        __float22half2_rn(make_float2(acc[mi][ni][2] * s1, acc[mi][ni][3] * s1));
            } else {
                float* C = (float*)Cv;
                if (gr0 < M)
                    *(float2*)(C + (size_t)gr0 * NCOLS + col) =
                        make_float2(acc[mi][ni][0] * s0, acc[mi][ni][1] * s0);
                if (gr0 + 8 < M)
                    *(float2*)(C + (size_t)(gr0 + 8) * NCOLS + col) =
                        make_float2(acc[mi][ni][2] * s1, acc[mi][ni][3] * s1);
            }
        }
    }
}

// ---------------- stream/event singletons (host resources, created once) ----------
namespace {
struct HxRes {
    cudaStream_t s_pre = nullptr, s_g3 = nullptr, s_g2 = nullptr;
    cudaEvent_t  e_fork = nullptr, e_w = nullptr, e_csr = nullptr,
                 e_g1 = nullptr, e_g3 = nullptr, e_gh1 = nullptr, e_g2 = nullptr,
                 e_zero = nullptr;
    HxRes() {
        cudaStreamCreateWithFlags(&s_pre, cudaStreamNonBlocking);
        cudaStreamCreateWithFlags(&s_g3,  cudaStreamNonBlocking);
        cudaStreamCreateWithFlags(&s_g2,  cudaStreamNonBlocking);
        cudaEventCreateWithFlags(&e_fork, cudaEventDisableTiming);
        cudaEventCreateWithFlags(&e_w,    cudaEventDisableTiming);
        cudaEventCreateWithFlags(&e_csr,  cudaEventDisableTiming);
        cudaEventCreateWithFlags(&e_g1,   cudaEventDisableTiming);
        cudaEventCreateWithFlags(&e_g3,   cudaEventDisableTiming);
        cudaEventCreateWithFlags(&e_gh1,  cudaEventDisableTiming);
        cudaEventCreateWithFlags(&e_g2,   cudaEventDisableTiming);
        cudaEventCreateWithFlags(&e_zero, cudaEventDisableTiming);
    }
};
HxRes g_res;
}

// ---------------- launch ----------------
extern "C" void kernel_launch(void* const* d_in, const int* in_sizes, int n_in,
                              void* d_out, int out_size)
{
    const float* features = (const float*)d_in[0];
    const float* noise    = (const float*)d_in[1];
    const float* W1       = (const float*)d_in[2];
    const float* b1       = (const float*)d_in[3];
    const float* W2       = (const float*)d_in[4];
    const float* b2       = (const float*)d_in[5];
    const float* W3       = (const float*)d_in[6];
    const float* b3       = (const float*)d_in[7];
    const float* fcW      = (const float*)d_in[8];
    const int*   src      = (const int*)d_in[9];
    const int*   dst      = (const int*)d_in[10];

    float* out     = (float*)d_out;
    float* z_out   = out;                                 // [NN, 128]
    float* h_out   = out + (size_t)NN * DOUT;             // [NN, 256]
    float* seq_out = h_out + (size_t)NN * DHID;           // [NN, 256]

    __half *pth, *phh, *pfh, *pw1, *pw23, *pfcw;
    float  *pon;
    cudaGetSymbolAddress((void**)&pth,  g_th);
    cudaGetSymbolAddress((void**)&phh,  g_hh);
    cudaGetSymbolAddress((void**)&pfh,  g_fh);
    cudaGetSymbolAddress((void**)&pw1,  g_w1h);
    cudaGetSymbolAddress((void**)&pw23, g_w23h);
    cudaGetSymbolAddress((void**)&pfcw, g_fcwh);
    cudaGetSymbolAddress((void**)&pon,  g_outnorm);

    const int T = 256;
    dim3 ggrid(2, (NN + 127) / 128);
    dim3 ggrid_lo(2, MID / 128);
    dim3 ggrid_hi(2, (NN - MID + 127) / 128);

    // ---- fork: compact prologue on side stream (counts are pre-zeroed) ----
    cudaEventRecord(g_res.e_fork, 0);
    cudaStreamWaitEvent(g_res.s_pre, g_res.e_fork, 0);
    k_conv_weights<<<768, T, 0, g_res.s_pre>>>(W1, W2, W3, fcW);
    cudaEventRecord(g_res.e_w, g_res.s_pre);
    k_degree<<<(NE / 2 + T - 1) / T, T, 0, g_res.s_pre>>>(src, dst);
    k_scan_p1n<<<SCAN_GRID, SCAN_B, 0, g_res.s_pre>>>();
    k_scan_p3f<<<SCAN_GRID, SCAN_B, 0, g_res.s_pre>>>();
    k_csr_fill<<<(NE + T - 1) / T, T, 0, g_res.s_pre>>>(src, dst);
    cudaEventRecord(g_res.e_csr, g_res.s_pre);
    // tail: re-zero counters in the shadow of main-stream work
    k_zero_counts<<<(NN + T - 1) / T, T, 0, g_res.s_pre>>>();
    cudaEventRecord(g_res.e_zero, g_res.s_pre);

    // ---- main: feature conversion, then gemm1 (fp16) ----
    k_conv_feat<<<(NN * (DIN / 4) + T - 1) / T, T>>>(features);
    cudaStreamWaitEvent(0, g_res.e_w, 0);
    k_gemm_f16<1><<<ggrid, T>>>(pfh, nullptr, pw1, pth, NN);
    cudaEventRecord(g_res.e_g1, 0);

    // ---- side: gemm3 (seq_fts) after gemm1, overlapping the rest ----
    cudaStreamWaitEvent(g_res.s_g3, g_res.e_g1, 0);
    k_gemm_f16<0><<<ggrid, T, 0, g_res.s_g3>>>(pfh, nullptr, pfcw, seq_out, NN);
    cudaEventRecord(g_res.e_g3, g_res.s_g3);

    // ---- main: join CSR; gather_h split into halves ----
    cudaStreamWaitEvent(0, g_res.e_csr, 0);
    k_gather_h<<<(MID * 32 + T - 1) / T, T>>>(pth, b1, h_out, phh, 0, MID);
    cudaEventRecord(g_res.e_gh1, 0);
    k_gather_h<<<((NN - MID) * 32 + T - 1) / T, T>>>(pth, b1, h_out, phh, MID, NN);

    // ---- side: gemm2 lower half overlaps gather_h upper half ----
    cudaStreamWaitEvent(g_res.s_g2, g_res.e_gh1, 0);
    k_gemm_f16<1><<<ggrid_lo, T, 0, g_res.s_g2>>>(phh, pon, pw23, pth, MID);
    cudaEventRecord(g_res.e_g2, g_res.s_g2);

    // ---- main: gemm2 upper half, join lower, gather_z ----
    k_gemm_f16<1><<<ggrid_hi, T>>>(phh + (size_t)MID * DHID, pon + MID, pw23,
                                   pth + (size_t)MID * DHID, NN - MID);
    cudaStreamWaitEvent(0, g_res.e_g2, 0);
    k_gather_z<<<(NN * 32 + T - 1) / T, T>>>(pth, b2, b3, noise, z_out);

    // ---- final joins: seq_fts + counter re-zero must complete before graph end ----
    cudaStreamWaitEvent(0, g_res.e_g3, 0);
    cudaStreamWaitEvent(0, g_res.e_zero, 0);
}

// round 14
// speedup vs baseline: 1.4204x; 1.0193x over previous
#include <cuda_runtime.h>
#include <cuda_fp16.h>
#include <cstdint>
#include <cstddef>

#define NN   50000
#define NE   800000
#define DIN  256
#define DHID 256
#define DOUT 128
#define MID  25088    // gather_h/gemm2 split point (multiple of 128)

#define SCAN_B 256
#define SCAN_GRID ((NN + SCAN_B - 1) / SCAN_B)   // 196

// ---------------- scratch (device globals; no allocation allowed) ----------------
// g_outc/g_inc rely on zero-initialization at module load; every call re-zeroes
// them at its tail (shadowed), so each invocation starts from zeros.
__device__ float g_outnorm[NN];
__device__ float g_innorm[NN];
__device__ int   g_outc[NN];
__device__ int   g_inc[NN];
__device__ int   g_rowptr[NN + 1];
__device__ int   g_cursor[NN];
__device__ int   g_poff[SCAN_B];                 // per-block inc sums
__device__ int   g_csrc[NE];                     // src node per CSR slot (by dst)
__device__ __half g_th[(size_t)NN * DHID];       // pre-agg features t (fp16)
__device__ __half g_hh[(size_t)NN * DHID];       // fp16 copy of h (gemm2 input)
__device__ __half g_fh[(size_t)NN * DIN];        // fp16 features
__device__ __half g_w1h[DIN * DHID];             // W1^T  [n][k] fp16
__device__ __half g_w23h[DHID * DHID];           // [W2|W3]^T [n][k] fp16
__device__ __half g_fcwh[DHID * DIN];            // fcW (already [n][k]) fp16

// ---------------- conversion kernels ----------------
__global__ void k_conv_feat(const float* __restrict__ f) {
    int i = blockIdx.x * blockDim.x + threadIdx.x;
    if (i >= NN * (DIN / 4)) return;
    float4 v = ((const float4*)f)[i];
    __half2 h0 = __float22half2_rn(make_float2(v.x, v.y));
    __half2 h1 = __float22half2_rn(make_float2(v.z, v.w));
    uint2 o;
    o.x = *(uint32_t*)&h0;
    o.y = *(uint32_t*)&h1;
    ((uint2*)g_fh)[i] = o;
}

// all weight conversions in one launch (196608 threads)
__global__ void k_conv_weights(const float* __restrict__ W1, const float* __restrict__ W2,
                               const float* __restrict__ W3, const float* __restrict__ fcW) {
    int t = blockIdx.x * blockDim.x + threadIdx.x;
    if (t < 65536) {                              // W1 -> g_w1h transposed
        int n = t >> 8, k = t & 255;
        g_w1h[t] = __float2half(W1[k * 256 + n]);
    } else if (t < 131072) {                      // fcW -> g_fcwh direct
        int i = t - 65536;
        g_fcwh[i] = __float2half(fcW[i]);
    } else {                                      // W2|W3 -> g_w23h transposed
        int i = t - 131072;                       // 0..65535
        int hs = i >> 15;                         // 0: W2, 1: W3
        int j = i & 32767;
        int n = j >> 8, k = j & 255;
        const float* S = hs ? W3 : W2;
        g_w23h[(size_t)(hs * 128 + n) * 256 + k] = __float2half(S[k * 128 + n]);
    }
}

// ---------------- degree / norm / CSR kernels ----------------
// 2 edges per thread
__global__ void k_degree(const int* __restrict__ src, const int* __restrict__ dst) {
    int e = (blockIdx.x * blockDim.x + threadIdx.x) * 2;
    if (e + 1 < NE) {
        int2 s = *(const int2*)(src + e);
        int2 d = *(const int2*)(dst + e);
        atomicAdd(&g_outc[s.x], 1);
        atomicAdd(&g_outc[s.y], 1);
        atomicAdd(&g_inc[d.x], 1);
        atomicAdd(&g_inc[d.y], 1);
    } else if (e < NE) {
        atomicAdd(&g_outc[src[e]], 1);
        atomicAdd(&g_inc[dst[e]], 1);
    }
}

// tail zeroing (runs shadowed at graph end; restores zero-state for next replay)
__global__ void k_zero_counts() {
    int i = blockIdx.x * blockDim.x + threadIdx.x;
    if (i < NN) { g_outc[i] = 0; g_inc[i] = 0; }
}

// phase 1 (fused with norms): per-block inc sums + out/in norms
__global__ void k_scan_p1n() {
    __shared__ int ws[8];
    int i = blockIdx.x * SCAN_B + threadIdx.x;
    int lane = threadIdx.x & 31, wid = threadIdx.x >> 5;
    int v = 0;
    if (i < NN) {
        int oc = g_outc[i];
        v = g_inc[i];
        g_outnorm[i] = rsqrtf(fmaxf((float)oc, 1.f));
        g_innorm[i]  = rsqrtf(fmaxf((float)v, 1.f));
    }
    int x = v;
#pragma unroll
    for (int o = 16; o > 0; o >>= 1) x += __shfl_down_sync(0xffffffffu, x, o);
    if (lane == 0) ws[wid] = x;
    __syncthreads();
    if (wid == 0) {
        int s = (lane < 8) ? ws[lane] : 0;
#pragma unroll
        for (int o = 4; o > 0; o >>= 1) s += __shfl_down_sync(0xffffffffu, s, o);
        if (lane == 0) g_poff[blockIdx.x] = s;
    }
}

// phase 2+3 fused: each block reduces g_poff[0..b) itself, then local scan.
__global__ void k_scan_p3f() {
    __shared__ int ws[8];
    __shared__ int s_off;
    const int b = blockIdx.x;
    int tid = threadIdx.x, lane = tid & 31, wid = tid >> 5;

    int p = (tid < b && tid < SCAN_GRID) ? g_poff[tid] : 0;
#pragma unroll
    for (int o = 16; o > 0; o >>= 1) p += __shfl_down_sync(0xffffffffu, p, o);
    if (lane == 0) ws[wid] = p;
    __syncthreads();
    if (wid == 0) {
        int s = (lane < 8) ? ws[lane] : 0;
#pragma unroll
        for (int o = 4; o > 0; o >>= 1) s += __shfl_down_sync(0xffffffffu, s, o);
        if (lane == 0) s_off = s;
    }
    __syncthreads();

    int i = b * SCAN_B + tid;
    int v = (i < NN) ? g_inc[i] : 0;
    int x = v;
#pragma unroll
    for (int o = 1; o < 32; o <<= 1) {
        int y = __shfl_up_sync(0xffffffffu, x, o);
        if (lane >= o) x += y;
    }
    __syncthreads();
    if (lane == 31) ws[wid] = x;
    __syncthreads();
    if (wid == 0 && lane < 8) {
        int s = ws[lane];
        int xs = s;
#pragma unroll
        for (int o = 1; o < 8; o <<= 1) {
            int y = __shfl_up_sync(0xffu, xs, o);
            if (lane >= o) xs += y;
        }
        ws[lane] = xs - s;
    }
    __syncthreads();
    if (i < NN) {
        int excl = s_off + ws[wid] + x - v;
        g_rowptr[i] = excl;
        g_cursor[i] = excl;
    }
    if (b == 0 && tid == 0) g_rowptr[NN] = NE;
}

__global__ void k_csr_fill(const int* __restrict__ src, const int* __restrict__ dst) {
    int e = blockIdx.x * blockDim.x + threadIdx.x;
    if (e < NE) {
        int pos = atomicAdd(&g_cursor[dst[e]], 1);
        g_csrc[pos] = src[e];
    }
}

// ---------------- fp16 gather SpMM + fused epilogues ----------------
__device__ __forceinline__ void acc8_f16(float* a, uint4 v, float s) {
    __half2 p0 = *(__half2*)&v.x;
    __half2 p1 = *(__half2*)&v.y;
    __half2 p2 = *(__half2*)&v.z;
    __half2 p3 = *(__half2*)&v.w;
    float2 f0 = __half22float2(p0);
    float2 f1 = __half22float2(p1);
    float2 f2 = __half22float2(p2);
    float2 f3 = __half22float2(p3);
    a[0] = fmaf(f0.x, s, a[0]); a[1] = fmaf(f0.y, s, a[1]);
    a[2] = fmaf(f1.x, s, a[2]); a[3] = fmaf(f1.y, s, a[3]);
    a[4] = fmaf(f2.x, s, a[4]); a[5] = fmaf(f2.y, s, a[5]);
    a[6] = fmaf(f3.x, s, a[6]); a[7] = fmaf(f3.y, s, a[7]);
}

// h = relu(in_norm * sum outnorm[src]*t[src] + b1) for nodes [n0, n1)
// 4-edge unroll: all 4 row loads + scales issued before accumulation (MLP=4)
__global__ void k_gather_h(const __half* __restrict__ t, const float* __restrict__ b1,
                           float* __restrict__ h, __half* __restrict__ hh,
                           int n0, int n1) {
    int node = n0 + ((blockIdx.x * blockDim.x + threadIdx.x) >> 5);
    int lane = threadIdx.x & 31;
    if (node >= n1) return;
    int beg = g_rowptr[node], end = g_rowptr[node + 1];
    float a[8];
#pragma unroll
    for (int i = 0; i < 8; i++) a[i] = 0.f;
    int j = beg;
    for (; j + 3 < end; j += 4) {
        int s0 = g_csrc[j],     s1 = g_csrc[j + 1];
        int s2 = g_csrc[j + 2], s3 = g_csrc[j + 3];
        float on0 = g_outnorm[s0], on1 = g_outnorm[s1];
        float on2 = g_outnorm[s2], on3 = g_outnorm[s3];
        uint4 v0 = ((const uint4*)(t + (size_t)s0 * DHID))[lane];
        uint4 v1 = ((const uint4*)(t + (size_t)s1 * DHID))[lane];
        uint4 v2 = ((const uint4*)(t + (size_t)s2 * DHID))[lane];
        uint4 v3 = ((const uint4*)(t + (size_t)s3 * DHID))[lane];
        acc8_f16(a, v0, on0);
        acc8_f16(a, v1, on1);
        acc8_f16(a, v2, on2);
        acc8_f16(a, v3, on3);
    }
    for (; j < end; j++) {
        int s0 = g_csrc[j];
        float on0 = g_outnorm[s0];
        uint4 v = ((const uint4*)(t + (size_t)s0 * DHID))[lane];
        acc8_f16(a, v, on0);
    }
    float s = g_innorm[node];
    const float* bp = b1 + lane * 8;
    float4 bb0 = *(const float4*)bp;
    float4 bb1 = *(const float4*)(bp + 4);
    float4 o0, o1;
    o0.x = fmaxf(fmaf(a[0], s, bb0.x), 0.f); o0.y = fmaxf(fmaf(a[1], s, bb0.y), 0.f);
    o0.z = fmaxf(fmaf(a[2], s, bb0.z), 0.f); o0.w = fmaxf(fmaf(a[3], s, bb0.w), 0.f);
    o1.x = fmaxf(fmaf(a[4], s, bb1.x), 0.f); o1.y = fmaxf(fmaf(a[5], s, bb1.y), 0.f);
    o1.z = fmaxf(fmaf(a[6], s, bb1.z), 0.f); o1.w = fmaxf(fmaf(a[7], s, bb1.w), 0.f);
    float* hp = h + (size_t)node * DHID + lane * 8;
    *(float4*)hp = o0;
    *(float4*)(hp + 4) = o1;
    __half2 q0 = __float22half2_rn(make_float2(o0.x, o0.y));
    __half2 q1 = __float22half2_rn(make_float2(o0.z, o0.w));
    __half2 q2 = __float22half2_rn(make_float2(o1.x, o1.y));
    __half2 q3 = __float22half2_rn(make_float2(o1.z, o1.w));
    uint4 q;
    q.x = *(uint32_t*)&q0; q.y = *(uint32_t*)&q1;
    q.z = *(uint32_t*)&q2; q.w = *(uint32_t*)&q3;
    ((uint4*)(hh + (size_t)node * DHID))[lane] = q;
}

// z = relu(mean*in + b2) + noise * exp(logstd*in + b3)   (4-edge unroll)
__global__ void k_gather_z(const __half* __restrict__ t,
                           const float* __restrict__ b2, const float* __restrict__ b3,
                           const float* __restrict__ noise, float* __restrict__ z) {
    int node = (blockIdx.x * blockDim.x + threadIdx.x) >> 5;
    int lane = threadIdx.x & 31;
    if (node >= NN) return;
    int beg = g_rowptr[node], end = g_rowptr[node + 1];
    float a[8];
#pragma unroll
    for (int i = 0; i < 8; i++) a[i] = 0.f;
    int j = beg;
    for (; j + 3 < end; j += 4) {
        int s0 = g_csrc[j],     s1 = g_csrc[j + 1];
        int s2 = g_csrc[j + 2], s3 = g_csrc[j + 3];
        uint4 v0 = ((const uint4*)(t + (size_t)s0 * DHID))[lane];
        uint4 v1 = ((const uint4*)(t + (size_t)s1 * DHID))[lane];
        uint4 v2 = ((const uint4*)(t + (size_t)s2 * DHID))[lane];
        uint4 v3 = ((const uint4*)(t + (size_t)s3 * DHID))[lane];
        acc8_f16(a, v0, 1.f);
        acc8_f16(a, v1, 1.f);
        acc8_f16(a, v2, 1.f);
        acc8_f16(a, v3, 1.f);
    }
    for (; j < end; j++) {
        uint4 v = ((const uint4*)(t + (size_t)g_csrc[j] * DHID))[lane];
        acc8_f16(a, v, 1.f);
    }
    float l[8];
#pragma unroll
    for (int i = 0; i < 8; i++) l[i] = __shfl_down_sync(0xffffffffu, a[i], 16);
    if (lane < 16) {
        float s = g_innorm[node];
        const float* bmp = b2 + lane * 8;
        const float* blp = b3 + lane * 8;
        const float* nvp = noise + (size_t)node * DOUT + lane * 8;
        float4 bm0 = *(const float4*)bmp,        bm1 = *(const float4*)(bmp + 4);
        float4 bl0 = *(const float4*)blp,        bl1 = *(const float4*)(blp + 4);
        float4 n0  = *(const float4*)nvp,        n1  = *(const float4*)(nvp + 4);
        float4 r0, r1;
        r0.x = fmaxf(fmaf(a[0], s, bm0.x), 0.f) + n0.x * expf(fmaf(l[0], s, bl0.x));
        r0.y = fmaxf(fmaf(a[1], s, bm0.y), 0.f) + n0.y * expf(fmaf(l[1], s, bl0.y));
        r0.z = fmaxf(fmaf(a[2], s, bm0.z), 0.f) + n0.z * expf(fmaf(l[2], s, bl0.z));
        r0.w = fmaxf(fmaf(a[3], s, bm0.w), 0.f) + n0.w * expf(fmaf(l[3], s, bl0.w));
        r1.x = fmaxf(fmaf(a[4], s, bm1.x), 0.f) + n1.x * expf(fmaf(l[4], s, bl1.x));
        r1.y = fmaxf(fmaf(a[5], s, bm1.y), 0.f) + n1.y * expf(fmaf(l[5], s, bl1.y));
        r1.z = fmaxf(fmaf(a[6], s, bm1.z), 0.f) + n1.z * expf(fmaf(l[6], s, bl1.z));
        r1.w = fmaxf(fmaf(a[7], s, bm1.w), 0.f) + n1.w * expf(fmaf(l[7], s, bl1.w));
        float* zp = z + (size_t)node * DOUT + lane * 8;
        *(float4*)zp = r0;
        *(float4*)(zp + 4) = r1;
    }
}

// ---------------- fp16 mma / cp.async helpers ----------------
__device__ __forceinline__ void mma_f16(float* c, const uint32_t* a, const uint32_t* b) {
    asm volatile(
        "mma.sync.aligned.m16n8k16.row.col.f32.f16.f16.f32 "
        "{%0,%1,%2,%3}, {%4,%5,%6,%7}, {%8,%9}, {%0,%1,%2,%3};"
        : "+f"(c[0]), "+f"(c[1]), "+f"(c[2]), "+f"(c[3])
        : "r"(a[0]), "r"(a[1]), "r"(a[2]), "r"(a[3]), "r"(b[0]), "r"(b[1]));
}

__device__ __forceinline__ void cp16(uint32_t dst, const void* src) {
    asm volatile("cp.async.cg.shared.global [%0], [%1], 16;" :: "r"(dst), "l"(src));
}
__device__ __forceinline__ void cp_commit() { asm volatile("cp.async.commit_group;"); }
template<int N>
__device__ __forceinline__ void cp_wait() { asm volatile("cp.async.wait_group %0;" :: "n"(N)); }

// ---------------- fp16 tensor-core GEMM (3-stage cp.async pipeline) ----------------
template<int OUTHALF>
__global__ void __launch_bounds__(256, 2)
k_gemm_f16(const __half* __restrict__ A, const float* __restrict__ rowscale,
           const __half* __restrict__ B, void* __restrict__ Cv, int M)
{
    constexpr int K = 256, NCOLS = 256;
    constexpr int BM = 128, BN = 128, BK = 32;
    constexpr int ALD = 40;
    constexpr int ST = 3;
    __shared__ __align__(16) __half As[ST][BM * ALD];
    __shared__ __align__(16) __half Bs[ST][BN * ALD];

    const int tid  = threadIdx.x;
    const int lane = tid & 31;
    const int warp = tid >> 5;
    const int row0 = blockIdx.y * BM;
    const int col0 = blockIdx.x * BN;
    const int warpM = (warp >> 2) * 64;
    const int warpN = (warp & 3) * 32;

    float acc[4][4][4];
#pragma unroll
    for (int i = 0; i < 4; i++)
#pragma unroll
        for (int j = 0; j < 4; j++)
#pragma unroll
            for (int r = 0; r < 4; r++) acc[i][j][r] = 0.f;

    auto stage = [&](int k0, int buf) {
#pragma unroll
        for (int i = 0; i < 2; i++) {
            int c = tid * 2 + i;
            int r = c >> 2;
            int off = (c & 3) * 8;
            int gr = row0 + r;
            if (gr >= M) gr = M - 1;
            cp16((uint32_t)__cvta_generic_to_shared(&As[buf][r * ALD + off]),
                 A + (size_t)gr * K + k0 + off);
            cp16((uint32_t)__cvta_generic_to_shared(&Bs[buf][r * ALD + off]),
                 B + (size_t)(col0 + r) * K + k0 + off);
        }
    };

    const int NT = K / BK;
    stage(0, 0);
    cp_commit();
    stage(BK, 1);
    cp_commit();

    for (int t = 0; t < NT; t++) {
        int buf = t % ST;
        if (t < NT - 1) cp_wait<1>(); else cp_wait<0>();
        __syncthreads();
        if (t + 2 < NT) {
            stage((t + 2) * BK, (t + 2) % ST);
            cp_commit();
        }

#pragma unroll
        for (int ks = 0; ks < 2; ks++) {
            const int kb = ks * 16 + (lane & 3) * 2;
            uint32_t a[4][4], b[4][2];
#pragma unroll
            for (int mi = 0; mi < 4; mi++) {
                const __half* ap = &As[buf][(warpM + mi * 16 + (lane >> 2)) * ALD + kb];
                a[mi][0] = *(const uint32_t*)ap;
                a[mi][1] = *(const uint32_t*)(ap + 8 * ALD);
                a[mi][2] = *(const uint32_t*)(ap + 8);
                a[mi][3] = *(const uint32_t*)(ap + 8 * ALD + 8);
            }
#pragma unroll
            for (int ni = 0; ni < 4; ni++) {
                const __half* bp = &Bs[buf][(warpN + ni * 8 + (lane >> 2)) * ALD + kb];
                b[ni][0] = *(const uint32_t*)bp;
                b[ni][1] = *(const uint32_t*)(bp + 8);
            }
#pragma unroll
            for (int mi = 0; mi < 4; mi++)
#pragma unroll
                for (int ni = 0; ni < 4; ni++)
                    mma_f16(acc[mi][ni], a[mi], b[ni]);
        }
    }

#pragma unroll
    for (int mi = 0; mi < 4; mi++) {
        int gr0 = row0 + warpM + mi * 16 + (lane >> 2);
        float s0 = 1.f, s1 = 1.f;
        if (rowscale) {
            if (gr0 < M)     s0 = rowscale[gr0];
            if (gr0 + 8 < M) s1 = rowscale[gr0 + 8];
        }
#pragma unroll
        for (int ni = 0; ni < 4; ni++) {
            int col = col0 + warpN + ni * 8 + (lane & 3) * 2;
            if constexpr (OUTHALF) {
                __half* Ch = (__half*)Cv;
                if (gr0 < M)
                    *(__half2*)(Ch + (size_t)gr0 * NCOLS + col) =
                        __float22half2_rn(make_float2(acc[mi][ni][0] * s0, acc[mi][ni][1] * s0));
                if (gr0 + 8 < M)
                    *(__half2*)(Ch + (size_t)(gr0 + 8) * NCOLS + col) =
                        __float22half2_rn(make_float2(acc[mi][ni][2] * s1, acc[mi][ni][3] * s1));
            } else {
                float* C = (float*)Cv;
                if (gr0 < M)
                    *(float2*)(C + (size_t)gr0 * NCOLS + col) =
                        make_float2(acc[mi][ni][0] * s0, acc[mi][ni][1] * s0);
                if (gr0 + 8 < M)
                    *(float2*)(C + (size_t)(gr0 + 8) * NCOLS + col) =
                        make_float2(acc[mi][ni][2] * s1, acc[mi][ni][3] * s1);
            }
        }
    }
}

// ---------------- stream/event singletons (host resources, created once) ----------
namespace {
struct HxRes {
    cudaStream_t s_pre = nullptr, s_g3 = nullptr, s_g2 = nullptr;
    cudaEvent_t  e_fork = nullptr, e_w = nullptr, e_csr = nullptr,
                 e_g1 = nullptr, e_g3 = nullptr, e_gh1 = nullptr, e_g2 = nullptr,
                 e_zero = nullptr;
    HxRes() {
        cudaStreamCreateWithFlags(&s_pre, cudaStreamNonBlocking);
        cudaStreamCreateWithFlags(&s_g3,  cudaStreamNonBlocking);
        cudaStreamCreateWithFlags(&s_g2,  cudaStreamNonBlocking);
        cudaEventCreateWithFlags(&e_fork, cudaEventDisableTiming);
        cudaEventCreateWithFlags(&e_w,    cudaEventDisableTiming);
        cudaEventCreateWithFlags(&e_csr,  cudaEventDisableTiming);
        cudaEventCreateWithFlags(&e_g1,   cudaEventDisableTiming);
        cudaEventCreateWithFlags(&e_g3,   cudaEventDisableTiming);
        cudaEventCreateWithFlags(&e_gh1,  cudaEventDisableTiming);
        cudaEventCreateWithFlags(&e_g2,   cudaEventDisableTiming);
        cudaEventCreateWithFlags(&e_zero, cudaEventDisableTiming);
    }
};
HxRes g_res;
}

// ---------------- launch ----------------
extern "C" void kernel_launch(void* const* d_in, const int* in_sizes, int n_in,
                              void* d_out, int out_size)
{
    const float* features = (const float*)d_in[0];
    const float* noise    = (const float*)d_in[1];
    const float* W1       = (const float*)d_in[2];
    const float* b1       = (const float*)d_in[3];
    const float* W2       = (const float*)d_in[4];
    const float* b2       = (const float*)d_in[5];
    const float* W3       = (const float*)d_in[6];
    const float* b3       = (const float*)d_in[7];
    const float* fcW      = (const float*)d_in[8];
    const int*   src      = (const int*)d_in[9];
    const int*   dst      = (const int*)d_in[10];

    float* out     = (float*)d_out;
    float* z_out   = out;                                 // [NN, 128]
    float* h_out   = out + (size_t)NN * DOUT;             // [NN, 256]
    float* seq_out = h_out + (size_t)NN * DHID;           // [NN, 256]

    __half *pth, *phh, *pfh, *pw1, *pw23, *pfcw;
    float  *pon;
    cudaGetSymbolAddress((void**)&pth,  g_th);
    cudaGetSymbolAddress((void**)&phh,  g_hh);
    cudaGetSymbolAddress((void**)&pfh,  g_fh);
    cudaGetSymbolAddress((void**)&pw1,  g_w1h);
    cudaGetSymbolAddress((void**)&pw23, g_w23h);
    cudaGetSymbolAddress((void**)&pfcw, g_fcwh);
    cudaGetSymbolAddress((void**)&pon,  g_outnorm);

    const int T = 256;
    dim3 ggrid(2, (NN + 127) / 128);
    dim3 ggrid_lo(2, MID / 128);
    dim3 ggrid_hi(2, (NN - MID + 127) / 128);

    // ---- fork: compact prologue on side stream (counts are pre-zeroed) ----
    cudaEventRecord(g_res.e_fork, 0);
    cudaStreamWaitEvent(g_res.s_pre, g_res.e_fork, 0);
    k_conv_weights<<<768, T, 0, g_res.s_pre>>>(W1, W2, W3, fcW);
    cudaEventRecord(g_res.e_w, g_res.s_pre);
    k_degree<<<(NE / 2 + T - 1) / T, T, 0, g_res.s_pre>>>(src, dst);
    k_scan_p1n<<<SCAN_GRID, SCAN_B, 0, g_res.s_pre>>>();
    k_scan_p3f<<<SCAN_GRID, SCAN_B, 0, g_res.s_pre>>>();
    k_csr_fill<<<(NE + T - 1) / T, T, 0, g_res.s_pre>>>(src, dst);
    cudaEventRecord(g_res.e_csr, g_res.s_pre);
    // tail: re-zero counters in the shadow of main-stream work
    k_zero_counts<<<(NN + T - 1) / T, T, 0, g_res.s_pre>>>();
    cudaEventRecord(g_res.e_zero, g_res.s_pre);

    // ---- main: feature conversion, then gemm1 (fp16) ----
    k_conv_feat<<<(NN * (DIN / 4) + T - 1) / T, T>>>(features);
    cudaStreamWaitEvent(0, g_res.e_w, 0);
    k_gemm_f16<1><<<ggrid, T>>>(pfh, nullptr, pw1, pth, NN);
    cudaEventRecord(g_res.e_g1, 0);

    // ---- side: gemm3 (seq_fts) after gemm1, overlapping the rest ----
    cudaStreamWaitEvent(g_res.s_g3, g_res.e_g1, 0);
    k_gemm_f16<0><<<ggrid, T, 0, g_res.s_g3>>>(pfh, nullptr, pfcw, seq_out, NN);
    cudaEventRecord(g_res.e_g3, g_res.s_g3);

    // ---- main: join CSR; gather_h split into halves ----
    cudaStreamWaitEvent(0, g_res.e_csr, 0);
    k_gather_h<<<(MID * 32 + T - 1) / T, T>>>(pth, b1, h_out, phh, 0, MID);
    cudaEventRecord(g_res.e_gh1, 0);
    k_gather_h<<<((NN - MID) * 32 + T - 1) / T, T>>>(pth, b1, h_out, phh, MID, NN);

    // ---- side: gemm2 lower half overlaps gather_h upper half ----
    cudaStreamWaitEvent(g_res.s_g2, g_res.e_gh1, 0);
    k_gemm_f16<1><<<ggrid_lo, T, 0, g_res.s_g2>>>(phh, pon, pw23, pth, MID);
    cudaEventRecord(g_res.e_g2, g_res.s_g2);

    // ---- main: gemm2 upper half, join lower, gather_z ----
    k_gemm_f16<1><<<ggrid_hi, T>>>(phh + (size_t)MID * DHID, pon + MID, pw23,
                                   pth + (size_t)MID * DHID, NN - MID);
    cudaStreamWaitEvent(0, g_res.e_g2, 0);
    k_gather_z<<<(NN * 32 + T - 1) / T, T>>>(pth, b2, b3, noise, z_out);

    // ---- final joins: seq_fts + counter re-zero must complete before graph end ----
    cudaStreamWaitEvent(0, g_res.e_g3, 0);
    cudaStreamWaitEvent(0, g_res.e_zero, 0);
}